// round 1
// baseline (speedup 1.0000x reference)
#include <cuda_runtime.h>
#include <cuda_bf16.h>

// Scratch: y[m][n], m = b*128 + seq (4096 rows), n in [0,1024):
//   n < 512  -> x1[b, seq, a=n]
//   n >= 512 -> x2[b, seq, a=n-512]
__device__ float g_y[4096 * 1024];

// ---------------------------------------------------------------------------
// Phase 1: fused SGEMM  y = x @ [W1;W2]^T + [b1;b2]
// M=4096, N=1024, K=512. fp32 (precision budget requires it this round).
// ---------------------------------------------------------------------------
#define BM 64
#define BN 64
#define BK 16

__global__ __launch_bounds__(256) void gemm_kernel(
    const float* __restrict__ x,
    const float* __restrict__ W1, const float* __restrict__ b1,
    const float* __restrict__ W2, const float* __restrict__ b2)
{
    __shared__ float As[BK][BM + 4];  // [k][m], pad 4 keeps float4 alignment
    __shared__ float Bs[BK][BN + 4];  // [k][n]

    const int mBase = blockIdx.x * BM;
    const int nBase = blockIdx.y * BN;

    const float* W    = (nBase < 512) ? W1 : W2;
    const float* bias = (nBase < 512) ? b1 : b2;
    const int    nOff = (nBase < 512) ? nBase : (nBase - 512);

    const int tid = threadIdx.x;       // 256 threads
    const int tm  = tid & 15;          // 16 m-groups of 4
    const int tn  = tid >> 4;          // 16 n-groups of 4

    float acc[4][4];
#pragma unroll
    for (int i = 0; i < 4; i++)
#pragma unroll
        for (int j = 0; j < 4; j++) acc[i][j] = 0.0f;

    for (int k0 = 0; k0 < 512; k0 += BK) {
        __syncthreads();
#pragma unroll
        for (int l = tid; l < BM * BK; l += 256) {
            int m = l >> 4, k = l & 15;
            As[k][m] = x[(mBase + m) * 512 + k0 + k];
        }
#pragma unroll
        for (int l = tid; l < BN * BK; l += 256) {
            int n = l >> 4, k = l & 15;
            Bs[k][n] = W[(nOff + n) * 512 + k0 + k];
        }
        __syncthreads();

#pragma unroll
        for (int k = 0; k < BK; k++) {
            float4 af = *(const float4*)&As[k][tm * 4];
            float4 bf = *(const float4*)&Bs[k][tn * 4];
            float av[4] = {af.x, af.y, af.z, af.w};
            float bv[4] = {bf.x, bf.y, bf.z, bf.w};
#pragma unroll
            for (int im = 0; im < 4; im++)
#pragma unroll
                for (int in = 0; in < 4; in++)
                    acc[im][in] = fmaf(av[im], bv[in], acc[im][in]);
        }
    }

    float bv[4];
#pragma unroll
    for (int in = 0; in < 4; in++) bv[in] = bias[nOff + tn * 4 + in];

#pragma unroll
    for (int im = 0; im < 4; im++) {
        int m = mBase + tm * 4 + im;
        float4 o;
        o.x = acc[im][0] + bv[0];
        o.y = acc[im][1] + bv[1];
        o.z = acc[im][2] + bv[2];
        o.w = acc[im][3] + bv[3];
        *(float4*)&g_y[m * 1024 + nBase + tn * 4] = o;
    }
}

// ---------------------------------------------------------------------------
// Phase 2: out[b,i,j] = sum_a Wout[a]*tanh(x1[b,j,a] + x2[b,i+1,a]) + bout
// MUFU-bound: 2 MUFU (EX2 + RCP) per element, accurate to ~1e-6 rel.
// Tiles: 32 j-rows x 32 i-rows, a-chunks of 128. Pad-129 smem rows => no
// bank conflicts for the [row][a] broadcast-read pattern.
// ---------------------------------------------------------------------------
#define TI 32
#define TJ 32
#define CH 128

__device__ __forceinline__ float tanh_acc(float s) {
    float em = __expf(-2.0f * fabsf(s));              // FMUL + EX2
    float r  = __fdividef(1.0f - em, 1.0f + em);      // 2 FADD + RCP + FMUL
    return copysignf(r, s);                           // LOP3
}

__global__ __launch_bounds__(256) void attn_kernel(
    const float* __restrict__ Wout,
    const float* __restrict__ bout,
    float* __restrict__ out)
{
    __shared__ float x1s[TJ][CH + 1];
    __shared__ float x2s[TI][CH + 1];
    __shared__ float ws[CH];

    const int b  = blockIdx.z;
    const int j0 = blockIdx.x * TJ;
    const int i0 = blockIdx.y * TI;   // i_out base (i_out = x2 row - 1)

    const int tid = threadIdx.x;
    const int j2  = tid & 15;         // j in {j0+j2, j0+j2+16}
    const int i2  = tid >> 4;         // i_out in {i0+i2, i0+i2+16}

    const float* __restrict__ Y = g_y + (size_t)b * 128 * 1024;

    float a00 = 0.f, a01 = 0.f, a10 = 0.f, a11 = 0.f;

    for (int ac = 0; ac < 512; ac += CH) {
        __syncthreads();
#pragma unroll
        for (int l = tid; l < TJ * CH; l += 256) {
            int r = l >> 7, c = l & (CH - 1);
            x1s[r][c] = Y[(j0 + r) * 1024 + ac + c];
            int irow = i0 + r + 1;            // x2 row (shift by 1)
            if (irow > 127) irow = 127;       // clamp (tile edge, values unused)
            x2s[r][c] = Y[irow * 1024 + 512 + ac + c];
        }
        if (tid < CH) ws[tid] = Wout[ac + tid];
        __syncthreads();

#pragma unroll 4
        for (int a = 0; a < CH; a++) {
            float w = ws[a];
            float p = x1s[j2][a];
            float q = x1s[j2 + 16][a];
            float u = x2s[i2][a];
            float v = x2s[i2 + 16][a];
            a00 = fmaf(tanh_acc(p + u), w, a00);
            a01 = fmaf(tanh_acc(q + u), w, a01);
            a10 = fmaf(tanh_acc(p + v), w, a10);
            a11 = fmaf(tanh_acc(q + v), w, a11);
        }
    }

    const float bo = __ldg(bout);
    // out shape (32, 127, 128)
    int iA = i0 + i2, iB = i0 + i2 + 16;
    int jA = j0 + j2, jB = j0 + j2 + 16;
    if (iA < 127) {
        out[((size_t)b * 127 + iA) * 128 + jA] = a00 + bo;
        out[((size_t)b * 127 + iA) * 128 + jB] = a01 + bo;
    }
    if (iB < 127) {
        out[((size_t)b * 127 + iB) * 128 + jA] = a10 + bo;
        out[((size_t)b * 127 + iB) * 128 + jB] = a11 + bo;
    }
}

// ---------------------------------------------------------------------------
extern "C" void kernel_launch(void* const* d_in, const int* in_sizes, int n_in,
                              void* d_out, int out_size)
{
    const float* x    = (const float*)d_in[0];
    const float* W1   = (const float*)d_in[1];
    const float* b1   = (const float*)d_in[2];
    const float* W2   = (const float*)d_in[3];
    const float* b2   = (const float*)d_in[4];
    const float* Wout = (const float*)d_in[5];
    const float* bout = (const float*)d_in[6];
    float* out = (float*)d_out;

    dim3 gGrid(4096 / BM, 1024 / BN);          // (64, 16)
    gemm_kernel<<<gGrid, 256>>>(x, W1, b1, W2, b2);

    dim3 aGrid(128 / TJ, (127 + TI - 1) / TI, 32);  // (4, 4, 32)
    attn_kernel<<<aGrid, 256>>>(Wout, bout, out);
}

// round 2
// speedup vs baseline: 1.1124x; 1.1124x over previous
#include <cuda_runtime.h>
#include <cuda_bf16.h>

// Scratch: g_y[m][n], m = b*128 + seq (4096 rows), n in [0,1024):
//   n < 512  -> tanh(x1[b, seq, a=n])
//   n >= 512 -> tanh(x2[b, seq, a=n-512])
// Storing TANH of the projections lets phase 2 use the tanh addition
// identity: tanh(p+u) = (tp+tu)/(1+tp*tu)  -> only 1 MUFU (RCP) per element.
__device__ float g_y[4096 * 1024];

// ---------------------------------------------------------------------------
// Phase 1: fused SGEMM  y = tanh(x @ [W1;W2]^T + [b1;b2])
// M=4096, N=1024, K=512. fp32 (precision budget requires it this round).
// ---------------------------------------------------------------------------
#define BM 64
#define BN 64
#define BK 16

__global__ __launch_bounds__(256) void gemm_kernel(
    const float* __restrict__ x,
    const float* __restrict__ W1, const float* __restrict__ b1,
    const float* __restrict__ W2, const float* __restrict__ b2)
{
    __shared__ float As[BK][BM + 4];  // [k][m], pad 4 keeps float4 alignment
    __shared__ float Bs[BK][BN + 4];  // [k][n]

    const int mBase = blockIdx.x * BM;
    const int nBase = blockIdx.y * BN;

    const float* W    = (nBase < 512) ? W1 : W2;
    const float* bias = (nBase < 512) ? b1 : b2;
    const int    nOff = (nBase < 512) ? nBase : (nBase - 512);

    const int tid = threadIdx.x;       // 256 threads
    const int tm  = tid & 15;          // 16 m-groups of 4
    const int tn  = tid >> 4;          // 16 n-groups of 4

    float acc[4][4];
#pragma unroll
    for (int i = 0; i < 4; i++)
#pragma unroll
        for (int j = 0; j < 4; j++) acc[i][j] = 0.0f;

    for (int k0 = 0; k0 < 512; k0 += BK) {
        __syncthreads();
#pragma unroll
        for (int l = tid; l < BM * BK; l += 256) {
            int m = l >> 4, k = l & 15;
            As[k][m] = x[(mBase + m) * 512 + k0 + k];
        }
#pragma unroll
        for (int l = tid; l < BN * BK; l += 256) {
            int n = l >> 4, k = l & 15;
            Bs[k][n] = W[(nOff + n) * 512 + k0 + k];
        }
        __syncthreads();

#pragma unroll
        for (int k = 0; k < BK; k++) {
            float4 af = *(const float4*)&As[k][tm * 4];
            float4 bf = *(const float4*)&Bs[k][tn * 4];
            float av[4] = {af.x, af.y, af.z, af.w};
            float bv[4] = {bf.x, bf.y, bf.z, bf.w};
#pragma unroll
            for (int im = 0; im < 4; im++)
#pragma unroll
                for (int in = 0; in < 4; in++)
                    acc[im][in] = fmaf(av[im], bv[in], acc[im][in]);
        }
    }

    float bv[4];
#pragma unroll
    for (int in = 0; in < 4; in++) bv[in] = bias[nOff + tn * 4 + in];

    // Epilogue: apply exact tanh (accurate library tanhf). 4M elements total,
    // cost is negligible vs the GEMM mainloop; buys 1 fewer MUFU per element
    // in phase 2 (266M elements).
#pragma unroll
    for (int im = 0; im < 4; im++) {
        int m = mBase + tm * 4 + im;
        float4 o;
        o.x = tanhf(acc[im][0] + bv[0]);
        o.y = tanhf(acc[im][1] + bv[1]);
        o.z = tanhf(acc[im][2] + bv[2]);
        o.w = tanhf(acc[im][3] + bv[3]);
        *(float4*)&g_y[m * 1024 + nBase + tn * 4] = o;
    }
}

// ---------------------------------------------------------------------------
// Phase 2: out[b,i,j] = sum_a Wout[a]*tanh(x1[b,j,a] + x2[b,i+1,a]) + bout
// With tp = tanh(x1), tu = tanh(x2) precomputed:
//   tanh(p+u) = (tp+tu) / (1 + tp*tu)
// Per element: FADD + FFMA + MUFU.RCP + FMUL + FFMA  -> MUFU-bound @ ~62us.
// ---------------------------------------------------------------------------
#define TI 32
#define TJ 32
#define CH 128

__global__ __launch_bounds__(256) void attn_kernel(
    const float* __restrict__ Wout,
    const float* __restrict__ bout,
    float* __restrict__ out)
{
    __shared__ float x1s[TJ][CH + 1];
    __shared__ float x2s[TI][CH + 1];
    __shared__ float ws[CH];

    const int b  = blockIdx.z;
    const int j0 = blockIdx.x * TJ;
    const int i0 = blockIdx.y * TI;   // i_out base (i_out = x2 row - 1)

    const int tid = threadIdx.x;
    const int j2  = tid & 15;         // j in {j0+j2, j0+j2+16}
    const int i2  = tid >> 4;         // i_out in {i0+i2, i0+i2+16}

    const float* __restrict__ Y = g_y + (size_t)b * 128 * 1024;

    float a00 = 0.f, a01 = 0.f, a10 = 0.f, a11 = 0.f;

    for (int ac = 0; ac < 512; ac += CH) {
        __syncthreads();
#pragma unroll
        for (int l = tid; l < TJ * CH; l += 256) {
            int r = l >> 7, c = l & (CH - 1);
            x1s[r][c] = Y[(j0 + r) * 1024 + ac + c];
            int irow = i0 + r + 1;            // x2 row (shift by 1)
            if (irow > 127) irow = 127;       // clamp (tile edge, values unused)
            x2s[r][c] = Y[irow * 1024 + 512 + ac + c];
        }
        if (tid < CH) ws[tid] = Wout[ac + tid];
        __syncthreads();

#pragma unroll 4
        for (int a = 0; a < CH; a++) {
            float w = ws[a];
            float p = x1s[j2][a];
            float q = x1s[j2 + 16][a];
            float u = x2s[i2][a];
            float v = x2s[i2 + 16][a];

            // tanh(p+u) = (p+u)/(1+p*u), operands already tanh'd
            float n00 = p + u, d00 = fmaf(p, u, 1.0f);
            float n01 = q + u, d01 = fmaf(q, u, 1.0f);
            float n10 = p + v, d10 = fmaf(p, v, 1.0f);
            float n11 = q + v, d11 = fmaf(q, v, 1.0f);

            a00 = fmaf(__fdividef(n00, d00), w, a00);
            a01 = fmaf(__fdividef(n01, d01), w, a01);
            a10 = fmaf(__fdividef(n10, d10), w, a10);
            a11 = fmaf(__fdividef(n11, d11), w, a11);
        }
    }

    const float bo = __ldg(bout);
    // out shape (32, 127, 128)
    int iA = i0 + i2, iB = i0 + i2 + 16;
    int jA = j0 + j2, jB = j0 + j2 + 16;
    if (iA < 127) {
        out[((size_t)b * 127 + iA) * 128 + jA] = a00 + bo;
        out[((size_t)b * 127 + iA) * 128 + jB] = a01 + bo;
    }
    if (iB < 127) {
        out[((size_t)b * 127 + iB) * 128 + jA] = a10 + bo;
        out[((size_t)b * 127 + iB) * 128 + jB] = a11 + bo;
    }
}

// ---------------------------------------------------------------------------
extern "C" void kernel_launch(void* const* d_in, const int* in_sizes, int n_in,
                              void* d_out, int out_size)
{
    const float* x    = (const float*)d_in[0];
    const float* W1   = (const float*)d_in[1];
    const float* b1   = (const float*)d_in[2];
    const float* W2   = (const float*)d_in[3];
    const float* b2   = (const float*)d_in[4];
    const float* Wout = (const float*)d_in[5];
    const float* bout = (const float*)d_in[6];
    float* out = (float*)d_out;

    dim3 gGrid(4096 / BM, 1024 / BN);          // (64, 16)
    gemm_kernel<<<gGrid, 256>>>(x, W1, b1, W2, b2);

    dim3 aGrid(128 / TJ, (127 + TI - 1) / TI, 32);  // (4, 4, 32)
    attn_kernel<<<aGrid, 256>>>(Wout, bout, out);
}

// round 4
// speedup vs baseline: 1.6827x; 1.5126x over previous
#include <cuda_runtime.h>
#include <cuda_bf16.h>
#include <cstdint>

// ---------------------------------------------------------------------------
// Scratch (device globals; no allocation allowed)
// ---------------------------------------------------------------------------
__device__ float g_y[4096 * 1024];            // tanh(x@[W1;W2]^T + b), 16MB
__device__ __nv_bfloat16 g_xh[4096 * 512];    // x hi (bf16)
__device__ __nv_bfloat16 g_xl[4096 * 512];    // x lo (bf16 residual)
__device__ __nv_bfloat16 g_wh[1024 * 512];    // [W1;W2] hi
__device__ __nv_bfloat16 g_wl[1024 * 512];    // [W1;W2] lo

static __device__ __forceinline__ uint32_t s2u(const void* p) {
    return (uint32_t)__cvta_generic_to_shared(p);
}

// ---------------------------------------------------------------------------
// Phase 0: split fp32 -> bf16 hi + bf16 lo
// ---------------------------------------------------------------------------
__global__ __launch_bounds__(256) void split_kernel(
    const float* __restrict__ src, __nv_bfloat16* __restrict__ dh,
    __nv_bfloat16* __restrict__ dl, int n)
{
    int i = blockIdx.x * 256 + threadIdx.x;
    if (i < n) {
        float v = src[i];
        __nv_bfloat16 h = __float2bfloat16(v);
        dh[i] = h;
        dl[i] = __float2bfloat16(v - __bfloat162float(h));
    }
}

// ---------------------------------------------------------------------------
// Phase 1: split-bf16 GEMM on mma.sync (HMMA.16816) — tcgen05 is rejected by
// this bench's plain sm_103 ptxas target, so warp-level MMA it is.
//   C = xh@Wh^T + xh@Wl^T + xl@Wh^T  (fp32 accum), epilogue tanh(C + bias).
// CTA 128x128, warp 64x32, K in 8 chunks of 64 via smem.
// ---------------------------------------------------------------------------
#define ROWB 144                 // bytes per smem tile row (64 bf16 + 8 pad)
#define TILEB (128 * ROWB)       // 18432 B per 128x64 bf16 tile
#define SM_AH 0
#define SM_AL TILEB
#define SM_BH (2 * TILEB)
#define SM_BL (3 * TILEB)
#define SM_TOTAL (4 * TILEB)     // 73728 B

#define LDM_X4(r0, r1, r2, r3, addr) \
    asm volatile("ldmatrix.sync.aligned.m8n8.x4.shared.b16 {%0,%1,%2,%3}, [%4];" \
                 : "=r"(r0), "=r"(r1), "=r"(r2), "=r"(r3) : "r"(addr))

#define MMA_BF16(c, a, b) \
    asm volatile("mma.sync.aligned.m16n8k16.row.col.f32.bf16.bf16.f32 " \
                 "{%0,%1,%2,%3}, {%4,%5,%6,%7}, {%8,%9}, {%0,%1,%2,%3};" \
                 : "+f"((c)[0]), "+f"((c)[1]), "+f"((c)[2]), "+f"((c)[3]) \
                 : "r"((a)[0]), "r"((a)[1]), "r"((a)[2]), "r"((a)[3]), \
                   "r"((b)[0]), "r"((b)[1]))

__global__ __launch_bounds__(256, 2) void gemm_tc_kernel(
    const float* __restrict__ b1, const float* __restrict__ b2)
{
    extern __shared__ char sm[];
    const uint32_t sb = s2u(sm);
    const int tid  = threadIdx.x;
    const int wid  = tid >> 5;
    const int lane = tid & 31;

    const int mBase = blockIdx.x * 128;
    const int nBase = blockIdx.y * 128;

    const int wm = wid & 1;       // 2 warp rows  (64 M each)
    const int wn = wid >> 1;      // 4 warp cols  (32 N each)

    // ldmatrix lane->row-address decomposition
    const int lr  = lane & 7;
    const int ls3 = (lane >> 3) & 1;
    const int ls4 = (lane >> 4) & 1;

    float acc[4][4][4];           // [mi][ni][frag]
#pragma unroll
    for (int mi = 0; mi < 4; mi++)
#pragma unroll
        for (int ni = 0; ni < 4; ni++)
#pragma unroll
            for (int f = 0; f < 4; f++) acc[mi][ni][f] = 0.0f;

    for (int kc = 0; kc < 8; kc++) {
        __syncthreads();
        // Load 4 tiles of 128 rows x 64 bf16 (128B payload per row, stride 144B).
#pragma unroll
        for (int t = 0; t < 16; t++) {
            int idx  = tid + t * 256;
            int tile = idx >> 10;           // 0:AH 1:AL 2:BH 3:BL
            int u    = idx & 1023;
            int row  = u >> 3;
            int c16  = u & 7;
            uint32_t dst = tile * TILEB + row * ROWB + c16 * 16;
            const __nv_bfloat16* gsrc;
            if (tile == 0)      gsrc = g_xh + (size_t)(mBase + row) * 512;
            else if (tile == 1) gsrc = g_xl + (size_t)(mBase + row) * 512;
            else if (tile == 2) gsrc = g_wh + (size_t)(nBase + row) * 512;
            else                gsrc = g_wl + (size_t)(nBase + row) * 512;
            *(uint4*)(sm + dst) = *(const uint4*)(gsrc + kc * 64 + c16 * 8);
        }
        __syncthreads();

#pragma unroll
        for (int ks = 0; ks < 4; ks++) {
            const int kb = ks * 16;
            // A address: lanes 0-7 m0-7@k0, 8-15 m8-15@k0, 16-23 m0-7@k8, 24-31 m8-15@k8
            // B address: lanes 0-7 n0-7@k0, 8-15 n0-7@k8, 16-23 n8-15@k0, 24-31 n8-15@k8
            uint32_t aoff = (uint32_t)((wm * 64 + ls3 * 8 + lr) * ROWB + (kb + ls4 * 8) * 2);
            uint32_t boff = (uint32_t)((wn * 32 + ls4 * 8 + lr) * ROWB + (kb + ls3 * 8) * 2);

            uint32_t bhf[4][2], blf[4][2];
#pragma unroll
            for (int nb = 0; nb < 2; nb++) {
                uint32_t addrH = sb + SM_BH + boff + nb * 16 * ROWB;
                uint32_t addrL = sb + SM_BL + boff + nb * 16 * ROWB;
                LDM_X4(bhf[2 * nb][0], bhf[2 * nb][1], bhf[2 * nb + 1][0], bhf[2 * nb + 1][1], addrH);
                LDM_X4(blf[2 * nb][0], blf[2 * nb][1], blf[2 * nb + 1][0], blf[2 * nb + 1][1], addrL);
            }

            uint32_t af[4][4];
            // --- product 1 & 2: AH * BH, AH * BL ---
#pragma unroll
            for (int mi = 0; mi < 4; mi++) {
                uint32_t addr = sb + SM_AH + aoff + mi * 16 * ROWB;
                LDM_X4(af[mi][0], af[mi][1], af[mi][2], af[mi][3], addr);
            }
#pragma unroll
            for (int mi = 0; mi < 4; mi++)
#pragma unroll
                for (int ni = 0; ni < 4; ni++)
                    MMA_BF16(acc[mi][ni], af[mi], bhf[ni]);
#pragma unroll
            for (int mi = 0; mi < 4; mi++)
#pragma unroll
                for (int ni = 0; ni < 4; ni++)
                    MMA_BF16(acc[mi][ni], af[mi], blf[ni]);
            // --- product 3: AL * BH ---
#pragma unroll
            for (int mi = 0; mi < 4; mi++) {
                uint32_t addr = sb + SM_AL + aoff + mi * 16 * ROWB;
                LDM_X4(af[mi][0], af[mi][1], af[mi][2], af[mi][3], addr);
            }
#pragma unroll
            for (int mi = 0; mi < 4; mi++)
#pragma unroll
                for (int ni = 0; ni < 4; ni++)
                    MMA_BF16(acc[mi][ni], af[mi], bhf[ni]);
        }
    }

    // Epilogue: bias + tanh + store fp32 to g_y.
    const float* bias = (nBase < 512) ? (b1 + nBase) : (b2 + (nBase - 512));
#pragma unroll
    for (int mi = 0; mi < 4; mi++) {
#pragma unroll
        for (int ni = 0; ni < 4; ni++) {
            int m = mBase + wm * 64 + mi * 16 + (lane >> 2);
            int nl = wn * 32 + ni * 8 + (lane & 3) * 2;
            float bv0 = __ldg(bias + nl);
            float bv1 = __ldg(bias + nl + 1);
            float2 o0, o1;
            o0.x = tanhf(acc[mi][ni][0] + bv0);
            o0.y = tanhf(acc[mi][ni][1] + bv1);
            o1.x = tanhf(acc[mi][ni][2] + bv0);
            o1.y = tanhf(acc[mi][ni][3] + bv1);
            *(float2*)(g_y + (size_t)m * 1024 + nBase + nl)       = o0;
            *(float2*)(g_y + (size_t)(m + 8) * 1024 + nBase + nl) = o1;
        }
    }
}

// ---------------------------------------------------------------------------
// Phase 2: out[b,i,j] = sum_a Wout[a]*tanh(x1[b,j,a] + x2[b,i+1,a]) + bout
// Operands pre-tanh'd: tanh(p+u) = (tp+tu)/(1+tp*tu) -> 1 MUFU.RCP / element.
// ---------------------------------------------------------------------------
#define TI 32
#define TJ 32
#define CH 128

__global__ __launch_bounds__(256) void attn_kernel(
    const float* __restrict__ Wout,
    const float* __restrict__ bout,
    float* __restrict__ out)
{
    __shared__ float x1s[TJ][CH + 1];
    __shared__ float x2s[TI][CH + 1];
    __shared__ float ws[CH];

    const int b  = blockIdx.z;
    const int j0 = blockIdx.x * TJ;
    const int i0 = blockIdx.y * TI;

    const int tid = threadIdx.x;
    const int j2  = tid & 15;
    const int i2  = tid >> 4;

    const float* __restrict__ Y = g_y + (size_t)b * 128 * 1024;

    float a00 = 0.f, a01 = 0.f, a10 = 0.f, a11 = 0.f;

    for (int ac = 0; ac < 512; ac += CH) {
        __syncthreads();
#pragma unroll
        for (int l = tid; l < TJ * CH; l += 256) {
            int r = l >> 7, c = l & (CH - 1);
            x1s[r][c] = Y[(j0 + r) * 1024 + ac + c];
            int irow = i0 + r + 1;
            if (irow > 127) irow = 127;
            x2s[r][c] = Y[irow * 1024 + 512 + ac + c];
        }
        if (tid < CH) ws[tid] = Wout[ac + tid];
        __syncthreads();

#pragma unroll 4
        for (int a = 0; a < CH; a++) {
            float w = ws[a];
            float p = x1s[j2][a];
            float q = x1s[j2 + 16][a];
            float u = x2s[i2][a];
            float v = x2s[i2 + 16][a];

            float n00 = p + u, d00 = fmaf(p, u, 1.0f);
            float n01 = q + u, d01 = fmaf(q, u, 1.0f);
            float n10 = p + v, d10 = fmaf(p, v, 1.0f);
            float n11 = q + v, d11 = fmaf(q, v, 1.0f);

            a00 = fmaf(__fdividef(n00, d00), w, a00);
            a01 = fmaf(__fdividef(n01, d01), w, a01);
            a10 = fmaf(__fdividef(n10, d10), w, a10);
            a11 = fmaf(__fdividef(n11, d11), w, a11);
        }
    }

    const float bo = __ldg(bout);
    int iA = i0 + i2, iB = i0 + i2 + 16;
    int jA = j0 + j2, jB = j0 + j2 + 16;
    if (iA < 127) {
        out[((size_t)b * 127 + iA) * 128 + jA] = a00 + bo;
        out[((size_t)b * 127 + iA) * 128 + jB] = a01 + bo;
    }
    if (iB < 127) {
        out[((size_t)b * 127 + iB) * 128 + jA] = a10 + bo;
        out[((size_t)b * 127 + iB) * 128 + jB] = a11 + bo;
    }
}

// ---------------------------------------------------------------------------
extern "C" void kernel_launch(void* const* d_in, const int* in_sizes, int n_in,
                              void* d_out, int out_size)
{
    const float* x    = (const float*)d_in[0];
    const float* W1   = (const float*)d_in[1];
    const float* b1   = (const float*)d_in[2];
    const float* W2   = (const float*)d_in[3];
    const float* b2   = (const float*)d_in[4];
    const float* Wout = (const float*)d_in[5];
    const float* bout = (const float*)d_in[6];
    float* out = (float*)d_out;

    __nv_bfloat16 *xh, *xl, *wh, *wl;
    cudaGetSymbolAddress((void**)&xh, g_xh);
    cudaGetSymbolAddress((void**)&xl, g_xl);
    cudaGetSymbolAddress((void**)&wh, g_wh);
    cudaGetSymbolAddress((void**)&wl, g_wl);

    // Phase 0: fp32 -> bf16 hi/lo splits
    split_kernel<<<(4096 * 512 + 255) / 256, 256>>>(x, xh, xl, 4096 * 512);
    split_kernel<<<(512 * 512 + 255) / 256, 256>>>(W1, wh, wl, 512 * 512);
    split_kernel<<<(512 * 512 + 255) / 256, 256>>>(W2, wh + 512 * 512, wl + 512 * 512,
                                                   512 * 512);

    // Phase 1: tensor-core (mma.sync) GEMM + tanh epilogue
    static bool attr_set = false;
    if (!attr_set) {
        cudaFuncSetAttribute(gemm_tc_kernel,
                             cudaFuncAttributeMaxDynamicSharedMemorySize, SM_TOTAL);
        attr_set = true;
    }
    gemm_tc_kernel<<<dim3(32, 8), 256, SM_TOTAL>>>(b1, b2);

    // Phase 2: additive attention
    dim3 aGrid(128 / TJ, (127 + TI - 1) / TI, 32);
    attn_kernel<<<aGrid, 256>>>(Wout, bout, out);
}

// round 5
// speedup vs baseline: 1.8861x; 1.1209x over previous
#include <cuda_runtime.h>
#include <cuda_bf16.h>
#include <cstdint>

// ---------------------------------------------------------------------------
// Scratch (device globals; no allocation allowed)
// ---------------------------------------------------------------------------
__device__ float g_y[4096 * 1024];            // tanh(x@[W1;W2]^T + b), 16MB
__device__ __nv_bfloat16 g_xh[4096 * 512];    // x hi (bf16)
__device__ __nv_bfloat16 g_xl[4096 * 512];    // x lo (bf16 residual)
__device__ __nv_bfloat16 g_wh[1024 * 512];    // [W1;W2] hi
__device__ __nv_bfloat16 g_wl[1024 * 512];    // [W1;W2] lo

static __device__ __forceinline__ uint32_t s2u(const void* p) {
    return (uint32_t)__cvta_generic_to_shared(p);
}
static __device__ __forceinline__ float frcp(float x) {
    float r;
    asm("rcp.approx.ftz.f32 %0, %1;" : "=f"(r) : "f"(x));
    return r;
}

// ---------------------------------------------------------------------------
// Phase 0: split fp32 -> bf16 hi + bf16 lo
// ---------------------------------------------------------------------------
__global__ __launch_bounds__(256) void split_kernel(
    const float* __restrict__ src, __nv_bfloat16* __restrict__ dh,
    __nv_bfloat16* __restrict__ dl, int n)
{
    int i = blockIdx.x * 256 + threadIdx.x;
    if (i < n) {
        float v = src[i];
        __nv_bfloat16 h = __float2bfloat16(v);
        dh[i] = h;
        dl[i] = __float2bfloat16(v - __bfloat162float(h));
    }
}

// ---------------------------------------------------------------------------
// Phase 1: split-bf16 GEMM on mma.sync (HMMA.16816), cp.async double buffer.
//   C = xh@Wh^T + xh@Wl^T + xl@Wh^T  (fp32 accum), epilogue tanh(C + bias).
// CTA 128x128, warp 64x32, K in 16 chunks of 32, 2-stage pipeline.
// ---------------------------------------------------------------------------
#define ROWB 80                  // 32 bf16 = 64B payload + 16B pad (ldmatrix CF)
#define TILEB (128 * ROWB)       // 10240 B per 128x32 bf16 tile
#define STAGEB (4 * TILEB)       // AH, AL, BH, BL
#define SM_TOTAL (2 * STAGEB)    // 81920 B

#define LDM_X4(r0, r1, r2, r3, addr) \
    asm volatile("ldmatrix.sync.aligned.m8n8.x4.shared.b16 {%0,%1,%2,%3}, [%4];" \
                 : "=r"(r0), "=r"(r1), "=r"(r2), "=r"(r3) : "r"(addr))

#define MMA_BF16(c, a, b) \
    asm volatile("mma.sync.aligned.m16n8k16.row.col.f32.bf16.bf16.f32 " \
                 "{%0,%1,%2,%3}, {%4,%5,%6,%7}, {%8,%9}, {%0,%1,%2,%3};" \
                 : "+f"((c)[0]), "+f"((c)[1]), "+f"((c)[2]), "+f"((c)[3]) \
                 : "r"((a)[0]), "r"((a)[1]), "r"((a)[2]), "r"((a)[3]), \
                   "r"((b)[0]), "r"((b)[1]))

#define CP_ASYNC16(dst, src) \
    asm volatile("cp.async.cg.shared.global [%0], [%1], 16;" \
                 :: "r"(dst), "l"(src))
#define CP_COMMIT() asm volatile("cp.async.commit_group;")
#define CP_WAIT1()  asm volatile("cp.async.wait_group 1;")
#define CP_WAIT0()  asm volatile("cp.async.wait_group 0;")

__global__ __launch_bounds__(256, 2) void gemm_tc_kernel(
    const float* __restrict__ b1, const float* __restrict__ b2)
{
    extern __shared__ char sm[];
    const uint32_t sb = s2u(sm);
    const int tid  = threadIdx.x;
    const int wid  = tid >> 5;
    const int lane = tid & 31;

    const int mBase = blockIdx.x * 128;
    const int nBase = blockIdx.y * 128;

    const int wm = wid & 1;       // 2 warp rows  (64 M each)
    const int wn = wid >> 1;      // 4 warp cols  (32 N each)

    const int lr  = lane & 7;
    const int ls3 = (lane >> 3) & 1;
    const int ls4 = (lane >> 4) & 1;

    // per-thread load slots: t=0,1 -> AH; 2,3 -> AL; 4,5 -> BH; 6,7 -> BL
    const int u_lo  = tid & 511;            // combined with t parity below
    float acc[4][4][4];
#pragma unroll
    for (int mi = 0; mi < 4; mi++)
#pragma unroll
        for (int ni = 0; ni < 4; ni++)
#pragma unroll
            for (int f = 0; f < 4; f++) acc[mi][ni][f] = 0.0f;

    auto issue_load = [&](int kc, int stage) {
#pragma unroll
        for (int t = 0; t < 8; t++) {
            int idx  = tid + t * 256;
            int tile = idx >> 9;           // 0:AH 1:AL 2:BH 3:BL
            int u    = idx & 511;
            int row  = u >> 2;
            int c    = u & 3;
            uint32_t dst = sb + stage * STAGEB + tile * TILEB + row * ROWB + c * 16;
            const __nv_bfloat16* gsrc;
            if (tile == 0)      gsrc = g_xh + (size_t)(mBase + row) * 512;
            else if (tile == 1) gsrc = g_xl + (size_t)(mBase + row) * 512;
            else if (tile == 2) gsrc = g_wh + (size_t)(nBase + row) * 512;
            else                gsrc = g_wl + (size_t)(nBase + row) * 512;
            CP_ASYNC16(dst, (const void*)(gsrc + kc * 32 + c * 8));
        }
        CP_COMMIT();
    };
    (void)u_lo;

    issue_load(0, 0);

    for (int kc = 0; kc < 16; kc++) {
        if (kc + 1 < 16) {
            issue_load(kc + 1, (kc + 1) & 1);
            CP_WAIT1();
        } else {
            CP_WAIT0();
        }
        __syncthreads();

        const uint32_t stg = sb + (kc & 1) * STAGEB;
#pragma unroll
        for (int ks = 0; ks < 2; ks++) {
            const int kb = ks * 16;
            uint32_t aoff = (uint32_t)((wm * 64 + ls3 * 8 + lr) * ROWB + (kb + ls4 * 8) * 2);
            uint32_t boff = (uint32_t)((wn * 32 + ls4 * 8 + lr) * ROWB + (kb + ls3 * 8) * 2);

            uint32_t bhf[4][2], blf[4][2];
#pragma unroll
            for (int nb = 0; nb < 2; nb++) {
                LDM_X4(bhf[2 * nb][0], bhf[2 * nb][1], bhf[2 * nb + 1][0], bhf[2 * nb + 1][1],
                       stg + 2 * TILEB + boff + nb * 16 * ROWB);
                LDM_X4(blf[2 * nb][0], blf[2 * nb][1], blf[2 * nb + 1][0], blf[2 * nb + 1][1],
                       stg + 3 * TILEB + boff + nb * 16 * ROWB);
            }

            uint32_t af[4][4];
#pragma unroll
            for (int mi = 0; mi < 4; mi++)
                LDM_X4(af[mi][0], af[mi][1], af[mi][2], af[mi][3],
                       stg + 0 * TILEB + aoff + mi * 16 * ROWB);
#pragma unroll
            for (int mi = 0; mi < 4; mi++)
#pragma unroll
                for (int ni = 0; ni < 4; ni++)
                    MMA_BF16(acc[mi][ni], af[mi], bhf[ni]);
#pragma unroll
            for (int mi = 0; mi < 4; mi++)
#pragma unroll
                for (int ni = 0; ni < 4; ni++)
                    MMA_BF16(acc[mi][ni], af[mi], blf[ni]);
#pragma unroll
            for (int mi = 0; mi < 4; mi++)
                LDM_X4(af[mi][0], af[mi][1], af[mi][2], af[mi][3],
                       stg + 1 * TILEB + aoff + mi * 16 * ROWB);
#pragma unroll
            for (int mi = 0; mi < 4; mi++)
#pragma unroll
                for (int ni = 0; ni < 4; ni++)
                    MMA_BF16(acc[mi][ni], af[mi], bhf[ni]);
        }
        __syncthreads();
    }

    // Epilogue: bias + tanh + store fp32 to g_y.
    const float* bias = (nBase < 512) ? (b1 + nBase) : (b2 + (nBase - 512));
#pragma unroll
    for (int mi = 0; mi < 4; mi++) {
#pragma unroll
        for (int ni = 0; ni < 4; ni++) {
            int m = mBase + wm * 64 + mi * 16 + (lane >> 2);
            int nl = wn * 32 + ni * 8 + (lane & 3) * 2;
            float bv0 = __ldg(bias + nl);
            float bv1 = __ldg(bias + nl + 1);
            float2 o0, o1;
            o0.x = tanhf(acc[mi][ni][0] + bv0);
            o0.y = tanhf(acc[mi][ni][1] + bv1);
            o1.x = tanhf(acc[mi][ni][2] + bv0);
            o1.y = tanhf(acc[mi][ni][3] + bv1);
            *(float2*)(g_y + (size_t)m * 1024 + nBase + nl)       = o0;
            *(float2*)(g_y + (size_t)(m + 8) * 1024 + nBase + nl) = o1;
        }
    }
}

// ---------------------------------------------------------------------------
// Phase 2: out[b,i,j] = sum_a Wout[a]*tanh(x1[b,j,a] + x2[b,i+1,a]) + bout
// With p = tanh(x1), u = tanh(x2), wp = w*p, wu = w*u precomputed per tile:
//   contribution = (wp + wu) * rcp(1 + p*u)
// -> 3 fma-pipe + 1 MUFU per element. Tile 64x64, thread 4x4, smem [a][row].
// ---------------------------------------------------------------------------
#define ACH 64                    // a-chunk
#define STR 68                    // row stride in floats (16B-aligned, padded)
#define AT_SMEM (4 * ACH * STR * 4)   // 4 arrays: p, wp, u, wu

__global__ __launch_bounds__(256) void attn_kernel(
    const float* __restrict__ Wout,
    const float* __restrict__ bout,
    float* __restrict__ out)
{
    extern __shared__ float smf[];
    float* s_p  = smf;                 // [ACH][STR]
    float* s_wp = smf + ACH * STR;
    float* s_u  = smf + 2 * ACH * STR;
    float* s_wu = smf + 3 * ACH * STR;

    const int b  = blockIdx.z;
    const int j0 = blockIdx.x * 64;
    const int i0 = blockIdx.y * 64;

    const int tid = threadIdx.x;
    const int jg  = tid & 15;          // j = j0 + 4*jg + {0..3}
    const int ig  = tid >> 4;          // i = i0 + 4*ig + {0..3}

    const float* __restrict__ Y = g_y + (size_t)b * 128 * 1024;

    // fill-phase indexing: a fixed per thread, rows strided
    const int fa = tid & 63;           // a within chunk
    const int fr = tid >> 6;           // row base (0..3), rows fr + 4t

    float acc[4][4];
#pragma unroll
    for (int m = 0; m < 4; m++)
#pragma unroll
        for (int n = 0; n < 4; n++) acc[m][n] = 0.0f;

    for (int ac = 0; ac < 512; ac += ACH) {
        __syncthreads();
        const float w = __ldg(Wout + ac + fa);
#pragma unroll
        for (int t = 0; t < 16; t++) {
            int r = fr + t * 4;                    // 0..63
            float p = Y[(size_t)(j0 + r) * 1024 + ac + fa];
            s_p [fa * STR + r] = p;
            s_wp[fa * STR + r] = w * p;
            int r2 = i0 + r + 1; if (r2 > 127) r2 = 127;
            float u = Y[(size_t)r2 * 1024 + 512 + ac + fa];
            s_u [fa * STR + r] = u;
            s_wu[fa * STR + r] = w * u;
        }
        __syncthreads();

#pragma unroll 2
        for (int a = 0; a < ACH; a++) {
            float4 p4  = *(const float4*)&s_p [a * STR + jg * 4];
            float4 wp4 = *(const float4*)&s_wp[a * STR + jg * 4];
            float4 u4  = *(const float4*)&s_u [a * STR + ig * 4];
            float4 wu4 = *(const float4*)&s_wu[a * STR + ig * 4];
            float pm[4] = {p4.x, p4.y, p4.z, p4.w};
            float wpm[4] = {wp4.x, wp4.y, wp4.z, wp4.w};
            float un[4] = {u4.x, u4.y, u4.z, u4.w};
            float wun[4] = {wu4.x, wu4.y, wu4.z, wu4.w};
#pragma unroll
            for (int n = 0; n < 4; n++)
#pragma unroll
                for (int m = 0; m < 4; m++) {
                    float den = fmaf(pm[m], un[n], 1.0f);
                    float num = wpm[m] + wun[n];
                    acc[n][m] = fmaf(num, frcp(den), acc[n][m]);
                }
        }
    }

    const float bo = __ldg(bout);
#pragma unroll
    for (int n = 0; n < 4; n++) {
        int i = i0 + ig * 4 + n;
        if (i < 127) {
            float4 o;
            o.x = acc[n][0] + bo;
            o.y = acc[n][1] + bo;
            o.z = acc[n][2] + bo;
            o.w = acc[n][3] + bo;
            *(float4*)(out + ((size_t)b * 127 + i) * 128 + j0 + jg * 4) = o;
        }
    }
}

// ---------------------------------------------------------------------------
extern "C" void kernel_launch(void* const* d_in, const int* in_sizes, int n_in,
                              void* d_out, int out_size)
{
    const float* x    = (const float*)d_in[0];
    const float* W1   = (const float*)d_in[1];
    const float* b1   = (const float*)d_in[2];
    const float* W2   = (const float*)d_in[3];
    const float* b2   = (const float*)d_in[4];
    const float* Wout = (const float*)d_in[5];
    const float* bout = (const float*)d_in[6];
    float* out = (float*)d_out;

    __nv_bfloat16 *xh, *xl, *wh, *wl;
    cudaGetSymbolAddress((void**)&xh, g_xh);
    cudaGetSymbolAddress((void**)&xl, g_xl);
    cudaGetSymbolAddress((void**)&wh, g_wh);
    cudaGetSymbolAddress((void**)&wl, g_wl);

    static bool attr_set = false;
    if (!attr_set) {
        cudaFuncSetAttribute(gemm_tc_kernel,
                             cudaFuncAttributeMaxDynamicSharedMemorySize, SM_TOTAL);
        cudaFuncSetAttribute(attn_kernel,
                             cudaFuncAttributeMaxDynamicSharedMemorySize, AT_SMEM);
        attr_set = true;
    }

    // Phase 0: fp32 -> bf16 hi/lo splits
    split_kernel<<<(4096 * 512 + 255) / 256, 256>>>(x, xh, xl, 4096 * 512);
    split_kernel<<<(512 * 512 + 255) / 256, 256>>>(W1, wh, wl, 512 * 512);
    split_kernel<<<(512 * 512 + 255) / 256, 256>>>(W2, wh + 512 * 512, wl + 512 * 512,
                                                   512 * 512);

    // Phase 1: tensor-core (mma.sync) GEMM + tanh epilogue, double-buffered
    gemm_tc_kernel<<<dim3(32, 8), 256, SM_TOTAL>>>(b1, b2);

    // Phase 2: additive attention (64x64 tiles, 4x4 per thread)
    attn_kernel<<<dim3(2, 2, 32), 256, AT_SMEM>>>(Wout, bout, out);
}

// round 6
// speedup vs baseline: 1.9954x; 1.0580x over previous
#include <cuda_runtime.h>
#include <cuda_bf16.h>
#include <cstdint>

// ---------------------------------------------------------------------------
// Scratch (device globals; no allocation allowed)
// ---------------------------------------------------------------------------
__device__ float g_y[4096 * 1024];            // tanh(x@[W1;W2]^T + b), 16MB
__device__ __nv_bfloat16 g_xh[4096 * 512];    // x hi (bf16)
__device__ __nv_bfloat16 g_xl[4096 * 512];    // x lo (bf16 residual)
__device__ __nv_bfloat16 g_wh[1024 * 512];    // [W1;W2] hi
__device__ __nv_bfloat16 g_wl[1024 * 512];    // [W1;W2] lo

static __device__ __forceinline__ uint32_t s2u(const void* p) {
    return (uint32_t)__cvta_generic_to_shared(p);
}
static __device__ __forceinline__ float frcp(float x) {
    float r;
    asm("rcp.approx.ftz.f32 %0, %1;" : "=f"(r) : "f"(x));
    return r;
}

// ---------------------------------------------------------------------------
// Phase 0: split fp32 -> bf16 hi + bf16 lo
// ---------------------------------------------------------------------------
__global__ __launch_bounds__(256) void split_kernel(
    const float* __restrict__ src, __nv_bfloat16* __restrict__ dh,
    __nv_bfloat16* __restrict__ dl, int n)
{
    int i = blockIdx.x * 256 + threadIdx.x;
    if (i < n) {
        float v = src[i];
        __nv_bfloat16 h = __float2bfloat16(v);
        dh[i] = h;
        dl[i] = __float2bfloat16(v - __bfloat162float(h));
    }
}

// ---------------------------------------------------------------------------
// Phase 1: split-bf16 GEMM on mma.sync (HMMA.16816) — R4 config (measured
// 43.7us; the R5 cp.async double-buffer regressed, reverted).
//   C = xh@Wh^T + xh@Wl^T + xl@Wh^T  (fp32 accum), epilogue tanh(C + bias).
// CTA 128x128, warp 64x32, K in 8 chunks of 64 via smem, 2 CTAs/SM.
// ---------------------------------------------------------------------------
#define ROWB 144                 // bytes per smem tile row (64 bf16 + 8 pad)
#define TILEB (128 * ROWB)       // 18432 B per 128x64 bf16 tile
#define SM_AH 0
#define SM_AL TILEB
#define SM_BH (2 * TILEB)
#define SM_BL (3 * TILEB)
#define SM_TOTAL (4 * TILEB)     // 73728 B

#define LDM_X4(r0, r1, r2, r3, addr) \
    asm volatile("ldmatrix.sync.aligned.m8n8.x4.shared.b16 {%0,%1,%2,%3}, [%4];" \
                 : "=r"(r0), "=r"(r1), "=r"(r2), "=r"(r3) : "r"(addr))

#define MMA_BF16(c, a, b) \
    asm volatile("mma.sync.aligned.m16n8k16.row.col.f32.bf16.bf16.f32 " \
                 "{%0,%1,%2,%3}, {%4,%5,%6,%7}, {%8,%9}, {%0,%1,%2,%3};" \
                 : "+f"((c)[0]), "+f"((c)[1]), "+f"((c)[2]), "+f"((c)[3]) \
                 : "r"((a)[0]), "r"((a)[1]), "r"((a)[2]), "r"((a)[3]), \
                   "r"((b)[0]), "r"((b)[1]))

__global__ __launch_bounds__(256, 2) void gemm_tc_kernel(
    const float* __restrict__ b1, const float* __restrict__ b2)
{
    extern __shared__ char sm[];
    const uint32_t sb = s2u(sm);
    const int tid  = threadIdx.x;
    const int wid  = tid >> 5;
    const int lane = tid & 31;

    const int mBase = blockIdx.x * 128;
    const int nBase = blockIdx.y * 128;

    const int wm = wid & 1;       // 2 warp rows  (64 M each)
    const int wn = wid >> 1;      // 4 warp cols  (32 N each)

    const int lr  = lane & 7;
    const int ls3 = (lane >> 3) & 1;
    const int ls4 = (lane >> 4) & 1;

    float acc[4][4][4];           // [mi][ni][frag]
#pragma unroll
    for (int mi = 0; mi < 4; mi++)
#pragma unroll
        for (int ni = 0; ni < 4; ni++)
#pragma unroll
            for (int f = 0; f < 4; f++) acc[mi][ni][f] = 0.0f;

    for (int kc = 0; kc < 8; kc++) {
        __syncthreads();
#pragma unroll
        for (int t = 0; t < 16; t++) {
            int idx  = tid + t * 256;
            int tile = idx >> 10;           // 0:AH 1:AL 2:BH 3:BL
            int u    = idx & 1023;
            int row  = u >> 3;
            int c16  = u & 7;
            uint32_t dst = tile * TILEB + row * ROWB + c16 * 16;
            const __nv_bfloat16* gsrc;
            if (tile == 0)      gsrc = g_xh + (size_t)(mBase + row) * 512;
            else if (tile == 1) gsrc = g_xl + (size_t)(mBase + row) * 512;
            else if (tile == 2) gsrc = g_wh + (size_t)(nBase + row) * 512;
            else                gsrc = g_wl + (size_t)(nBase + row) * 512;
            *(uint4*)(sm + dst) = *(const uint4*)(gsrc + kc * 64 + c16 * 8);
        }
        __syncthreads();

#pragma unroll
        for (int ks = 0; ks < 4; ks++) {
            const int kb = ks * 16;
            uint32_t aoff = (uint32_t)((wm * 64 + ls3 * 8 + lr) * ROWB + (kb + ls4 * 8) * 2);
            uint32_t boff = (uint32_t)((wn * 32 + ls4 * 8 + lr) * ROWB + (kb + ls3 * 8) * 2);

            uint32_t bhf[4][2], blf[4][2];
#pragma unroll
            for (int nb = 0; nb < 2; nb++) {
                LDM_X4(bhf[2 * nb][0], bhf[2 * nb][1], bhf[2 * nb + 1][0], bhf[2 * nb + 1][1],
                       sb + SM_BH + boff + nb * 16 * ROWB);
                LDM_X4(blf[2 * nb][0], blf[2 * nb][1], blf[2 * nb + 1][0], blf[2 * nb + 1][1],
                       sb + SM_BL + boff + nb * 16 * ROWB);
            }

            uint32_t af[4][4];
#pragma unroll
            for (int mi = 0; mi < 4; mi++)
                LDM_X4(af[mi][0], af[mi][1], af[mi][2], af[mi][3],
                       sb + SM_AH + aoff + mi * 16 * ROWB);
#pragma unroll
            for (int mi = 0; mi < 4; mi++)
#pragma unroll
                for (int ni = 0; ni < 4; ni++)
                    MMA_BF16(acc[mi][ni], af[mi], bhf[ni]);
#pragma unroll
            for (int mi = 0; mi < 4; mi++)
#pragma unroll
                for (int ni = 0; ni < 4; ni++)
                    MMA_BF16(acc[mi][ni], af[mi], blf[ni]);
#pragma unroll
            for (int mi = 0; mi < 4; mi++)
                LDM_X4(af[mi][0], af[mi][1], af[mi][2], af[mi][3],
                       sb + SM_AL + aoff + mi * 16 * ROWB);
#pragma unroll
            for (int mi = 0; mi < 4; mi++)
#pragma unroll
                for (int ni = 0; ni < 4; ni++)
                    MMA_BF16(acc[mi][ni], af[mi], bhf[ni]);
        }
    }

    // Epilogue: bias + tanh + store fp32 to g_y.
    const float* bias = (nBase < 512) ? (b1 + nBase) : (b2 + (nBase - 512));
#pragma unroll
    for (int mi = 0; mi < 4; mi++) {
#pragma unroll
        for (int ni = 0; ni < 4; ni++) {
            int m = mBase + wm * 64 + mi * 16 + (lane >> 2);
            int nl = wn * 32 + ni * 8 + (lane & 3) * 2;
            float bv0 = __ldg(bias + nl);
            float bv1 = __ldg(bias + nl + 1);
            float2 o0, o1;
            o0.x = tanhf(acc[mi][ni][0] + bv0);
            o0.y = tanhf(acc[mi][ni][1] + bv1);
            o1.x = tanhf(acc[mi][ni][2] + bv0);
            o1.y = tanhf(acc[mi][ni][3] + bv1);
            *(float2*)(g_y + (size_t)m * 1024 + nBase + nl)       = o0;
            *(float2*)(g_y + (size_t)(m + 8) * 1024 + nBase + nl) = o1;
        }
    }
}

// ---------------------------------------------------------------------------
// Phase 2: out[b,i,j] = sum_a Wout[a]*tanh(x1[b,j,a] + x2[b,i+1,a]) + bout
// contribution = (wp + wu) * rcp(1 + p*u); 3 fma-pipe + 1 MUFU per element.
// Tile 64i x 32j, per-thread 4i x 2j, 256 blocks -> 2 CTAs/SM, 4 warps/SMSP
// so the MUFU floor (8 cyc/warp-elem) binds instead of issue.
// ---------------------------------------------------------------------------
#define ACH   64
#define STRJ  34                  // 32 j + 2 pad (keeps float2 align, kills STS conflicts)
#define STRI  68                  // 64 i + 4 pad (keeps float4 align)
#define AT_SMEM ((2 * ACH * STRJ + 2 * ACH * STRI) * 4)   // 52224 B

__global__ __launch_bounds__(256) void attn_kernel(
    const float* __restrict__ Wout,
    const float* __restrict__ bout,
    float* __restrict__ out)
{
    extern __shared__ float smf[];
    float* s_p  = smf;                           // [ACH][STRJ]
    float* s_wp = smf + ACH * STRJ;              // [ACH][STRJ]
    float* s_u  = smf + 2 * ACH * STRJ;          // [ACH][STRI]
    float* s_wu = s_u + ACH * STRI;              // [ACH][STRI]

    const int b  = blockIdx.z;
    const int j0 = blockIdx.x * 32;
    const int i0 = blockIdx.y * 64;

    const int tid = threadIdx.x;
    const int jg  = tid & 15;          // j = j0 + 2*jg + {0,1}
    const int ig  = tid >> 4;          // i = i0 + 4*ig + {0..3}

    const float* __restrict__ Y = g_y + (size_t)b * 128 * 1024;

    // fill-phase indexing: a = tid&63 fixed per thread, rows strided by 4
    const int fa = tid & 63;
    const int fr = tid >> 6;           // 0..3

    float acc[4][2];
#pragma unroll
    for (int n = 0; n < 4; n++) { acc[n][0] = 0.0f; acc[n][1] = 0.0f; }

    for (int ac = 0; ac < 512; ac += ACH) {
        __syncthreads();
        const float w = __ldg(Wout + ac + fa);
        // p/wp: 32 j-rows
#pragma unroll
        for (int t = 0; t < 8; t++) {
            int r = fr + t * 4;                    // 0..31
            float p = Y[(size_t)(j0 + r) * 1024 + ac + fa];
            s_p [fa * STRJ + r] = p;
            s_wp[fa * STRJ + r] = w * p;
        }
        // u/wu: 64 i-rows (shifted by 1, clamped at edge; clamped values unused)
#pragma unroll
        for (int t = 0; t < 16; t++) {
            int r = fr + t * 4;                    // 0..63
            int r2 = i0 + r + 1; if (r2 > 127) r2 = 127;
            float u = Y[(size_t)r2 * 1024 + 512 + ac + fa];
            s_u [fa * STRI + r] = u;
            s_wu[fa * STRI + r] = w * u;
        }
        __syncthreads();

#pragma unroll 2
        for (int a = 0; a < ACH; a++) {
            float2 p2  = *(const float2*)&s_p [a * STRJ + jg * 2];
            float2 wp2 = *(const float2*)&s_wp[a * STRJ + jg * 2];
            float4 u4  = *(const float4*)&s_u [a * STRI + ig * 4];
            float4 wu4 = *(const float4*)&s_wu[a * STRI + ig * 4];
            float pm[2]  = {p2.x, p2.y};
            float wpm[2] = {wp2.x, wp2.y};
            float un[4]  = {u4.x, u4.y, u4.z, u4.w};
            float wun[4] = {wu4.x, wu4.y, wu4.z, wu4.w};
#pragma unroll
            for (int n = 0; n < 4; n++)
#pragma unroll
                for (int m = 0; m < 2; m++) {
                    float den = fmaf(pm[m], un[n], 1.0f);
                    float num = wpm[m] + wun[n];
                    acc[n][m] = fmaf(num, frcp(den), acc[n][m]);
                }
        }
    }

    const float bo = __ldg(bout);
#pragma unroll
    for (int n = 0; n < 4; n++) {
        int i = i0 + ig * 4 + n;
        if (i < 127) {
            float2 o;
            o.x = acc[n][0] + bo;
            o.y = acc[n][1] + bo;
            *(float2*)(out + ((size_t)b * 127 + i) * 128 + j0 + jg * 2) = o;
        }
    }
}

// ---------------------------------------------------------------------------
extern "C" void kernel_launch(void* const* d_in, const int* in_sizes, int n_in,
                              void* d_out, int out_size)
{
    const float* x    = (const float*)d_in[0];
    const float* W1   = (const float*)d_in[1];
    const float* b1   = (const float*)d_in[2];
    const float* W2   = (const float*)d_in[3];
    const float* b2   = (const float*)d_in[4];
    const float* Wout = (const float*)d_in[5];
    const float* bout = (const float*)d_in[6];
    float* out = (float*)d_out;

    __nv_bfloat16 *xh, *xl, *wh, *wl;
    cudaGetSymbolAddress((void**)&xh, g_xh);
    cudaGetSymbolAddress((void**)&xl, g_xl);
    cudaGetSymbolAddress((void**)&wh, g_wh);
    cudaGetSymbolAddress((void**)&wl, g_wl);

    static bool attr_set = false;
    if (!attr_set) {
        cudaFuncSetAttribute(gemm_tc_kernel,
                             cudaFuncAttributeMaxDynamicSharedMemorySize, SM_TOTAL);
        cudaFuncSetAttribute(attn_kernel,
                             cudaFuncAttributeMaxDynamicSharedMemorySize, AT_SMEM);
        attr_set = true;
    }

    // Phase 0: fp32 -> bf16 hi/lo splits
    split_kernel<<<(4096 * 512 + 255) / 256, 256>>>(x, xh, xl, 4096 * 512);
    split_kernel<<<(512 * 512 + 255) / 256, 256>>>(W1, wh, wl, 512 * 512);
    split_kernel<<<(512 * 512 + 255) / 256, 256>>>(W2, wh + 512 * 512, wl + 512 * 512,
                                                   512 * 512);

    // Phase 1: tensor-core (mma.sync) GEMM + tanh epilogue
    gemm_tc_kernel<<<dim3(32, 8), 256, SM_TOTAL>>>(b1, b2);

    // Phase 2: additive attention (64i x 32j tiles, 4x2 per thread, 256 blocks)
    attn_kernel<<<dim3(4, 2, 32), 256, AT_SMEM>>>(Wout, bout, out);
}

// round 7
// speedup vs baseline: 2.0601x; 1.0324x over previous
#include <cuda_runtime.h>
#include <cuda_bf16.h>
#include <cstdint>

// ---------------------------------------------------------------------------
// Scratch (device globals; no allocation allowed)
// ---------------------------------------------------------------------------
__device__ float g_y[4096 * 1024];            // tanh(x@[W1;W2]^T + b), 16MB
__device__ __nv_bfloat16 g_wh[1024 * 512];    // [W1;W2] hi
__device__ __nv_bfloat16 g_wl[1024 * 512];    // [W1;W2] lo

static __device__ __forceinline__ uint32_t s2u(const void* p) {
    return (uint32_t)__cvta_generic_to_shared(p);
}
static __device__ __forceinline__ float frcp(float x) {
    float r;
    asm("rcp.approx.ftz.f32 %0, %1;" : "=f"(r) : "f"(x));
    return r;
}

// ---------------------------------------------------------------------------
// Phase 0: split fp32 -> bf16 hi + bf16 lo (weights only; x is split on the
// fly inside the GEMM load path — same bytes, saves a 16MB pass)
// ---------------------------------------------------------------------------
__global__ __launch_bounds__(256) void split_kernel(
    const float* __restrict__ src, __nv_bfloat16* __restrict__ dh,
    __nv_bfloat16* __restrict__ dl, int n)
{
    int i = blockIdx.x * 256 + threadIdx.x;
    if (i < n) {
        float v = src[i];
        __nv_bfloat16 h = __float2bfloat16(v);
        dh[i] = h;
        dl[i] = __float2bfloat16(v - __bfloat162float(h));
    }
}

// ---------------------------------------------------------------------------
// Phase 1: split-bf16 GEMM on mma.sync (HMMA.16816).
//   C = xh@Wh^T + xh@Wl^T + xl@Wh^T  (fp32 accum), epilogue tanh(C + bias).
// CTA 128x128, warp 64x32, K in 8 chunks of 64 via smem, 2 CTAs/SM.
// x is loaded fp32 and hi/lo-split during the smem store.
// ---------------------------------------------------------------------------
#define ROWB 144                 // bytes per smem tile row (64 bf16 + 8 pad)
#define TILEB (128 * ROWB)       // 18432 B per 128x64 bf16 tile
#define SM_AH 0
#define SM_AL TILEB
#define SM_BH (2 * TILEB)
#define SM_BL (3 * TILEB)
#define SM_TOTAL (4 * TILEB)     // 73728 B

#define LDM_X4(r0, r1, r2, r3, addr) \
    asm volatile("ldmatrix.sync.aligned.m8n8.x4.shared.b16 {%0,%1,%2,%3}, [%4];" \
                 : "=r"(r0), "=r"(r1), "=r"(r2), "=r"(r3) : "r"(addr))

#define MMA_BF16(c, a, b) \
    asm volatile("mma.sync.aligned.m16n8k16.row.col.f32.bf16.bf16.f32 " \
                 "{%0,%1,%2,%3}, {%4,%5,%6,%7}, {%8,%9}, {%0,%1,%2,%3};" \
                 : "+f"((c)[0]), "+f"((c)[1]), "+f"((c)[2]), "+f"((c)[3]) \
                 : "r"((a)[0]), "r"((a)[1]), "r"((a)[2]), "r"((a)[3]), \
                   "r"((b)[0]), "r"((b)[1]))

__global__ __launch_bounds__(256, 2) void gemm_tc_kernel(
    const float* __restrict__ x,
    const float* __restrict__ b1, const float* __restrict__ b2)
{
    extern __shared__ char sm[];
    const uint32_t sb = s2u(sm);
    const int tid  = threadIdx.x;
    const int wid  = tid >> 5;
    const int lane = tid & 31;

    const int mBase = blockIdx.x * 128;
    const int nBase = blockIdx.y * 128;

    const int wm = wid & 1;       // 2 warp rows  (64 M each)
    const int wn = wid >> 1;      // 4 warp cols  (32 N each)

    const int lr  = lane & 7;
    const int ls3 = (lane >> 3) & 1;
    const int ls4 = (lane >> 4) & 1;

    float acc[4][4][4];           // [mi][ni][frag]
#pragma unroll
    for (int mi = 0; mi < 4; mi++)
#pragma unroll
        for (int ni = 0; ni < 4; ni++)
#pragma unroll
            for (int f = 0; f < 4; f++) acc[mi][ni][f] = 0.0f;

    for (int kc = 0; kc < 8; kc++) {
        __syncthreads();

        // --- A tiles: load x fp32, split hi/lo during STS ---
        // 2048 float4 per chunk (128 rows x 16 float4), 8 per thread.
        float4 va[8];
#pragma unroll
        for (int t = 0; t < 8; t++) {
            int idx = tid + t * 256;
            int row = idx >> 4;         // 0..127
            int c4  = idx & 15;         // float4 index within 64-float row
            va[t] = *(const float4*)(x + (size_t)(mBase + row) * 512 + kc * 64 + c4 * 4);
        }
        // --- B tiles: pre-split W, straight uint4 copy ---
#pragma unroll
        for (int t = 0; t < 8; t++) {
            int idx  = tid + t * 256;
            int tile = idx >> 10;           // 0:BH 1:BL
            int u    = idx & 1023;
            int row  = u >> 3;
            int c16  = u & 7;
            const __nv_bfloat16* gsrc = (tile == 0 ? g_wh : g_wl) + (size_t)(nBase + row) * 512;
            *(uint4*)(sm + (2 + tile) * TILEB + row * ROWB + c16 * 16) =
                *(const uint4*)(gsrc + kc * 64 + c16 * 8);
        }
#pragma unroll
        for (int t = 0; t < 8; t++) {
            int idx = tid + t * 256;
            int row = idx >> 4;
            int c4  = idx & 15;
            uint32_t off = row * ROWB + c4 * 8;
            __nv_bfloat162 h01 = __float22bfloat162_rn(make_float2(va[t].x, va[t].y));
            __nv_bfloat162 h23 = __float22bfloat162_rn(make_float2(va[t].z, va[t].w));
            float2 hf01 = __bfloat1622float2(h01);
            float2 hf23 = __bfloat1622float2(h23);
            __nv_bfloat162 l01 = __float22bfloat162_rn(
                make_float2(va[t].x - hf01.x, va[t].y - hf01.y));
            __nv_bfloat162 l23 = __float22bfloat162_rn(
                make_float2(va[t].z - hf23.x, va[t].w - hf23.y));
            uint2 hh, ll;
            hh.x = *(uint32_t*)&h01; hh.y = *(uint32_t*)&h23;
            ll.x = *(uint32_t*)&l01; ll.y = *(uint32_t*)&l23;
            *(uint2*)(sm + SM_AH + off) = hh;
            *(uint2*)(sm + SM_AL + off) = ll;
        }
        __syncthreads();

#pragma unroll
        for (int ks = 0; ks < 4; ks++) {
            const int kb = ks * 16;
            uint32_t aoff = (uint32_t)((wm * 64 + ls3 * 8 + lr) * ROWB + (kb + ls4 * 8) * 2);
            uint32_t boff = (uint32_t)((wn * 32 + ls4 * 8 + lr) * ROWB + (kb + ls3 * 8) * 2);

            uint32_t bhf[4][2], blf[4][2];
#pragma unroll
            for (int nb = 0; nb < 2; nb++) {
                LDM_X4(bhf[2 * nb][0], bhf[2 * nb][1], bhf[2 * nb + 1][0], bhf[2 * nb + 1][1],
                       sb + SM_BH + boff + nb * 16 * ROWB);
                LDM_X4(blf[2 * nb][0], blf[2 * nb][1], blf[2 * nb + 1][0], blf[2 * nb + 1][1],
                       sb + SM_BL + boff + nb * 16 * ROWB);
            }

            uint32_t af[4][4];
#pragma unroll
            for (int mi = 0; mi < 4; mi++)
                LDM_X4(af[mi][0], af[mi][1], af[mi][2], af[mi][3],
                       sb + SM_AH + aoff + mi * 16 * ROWB);
#pragma unroll
            for (int mi = 0; mi < 4; mi++)
#pragma unroll
                for (int ni = 0; ni < 4; ni++)
                    MMA_BF16(acc[mi][ni], af[mi], bhf[ni]);
#pragma unroll
            for (int mi = 0; mi < 4; mi++)
#pragma unroll
                for (int ni = 0; ni < 4; ni++)
                    MMA_BF16(acc[mi][ni], af[mi], blf[ni]);
#pragma unroll
            for (int mi = 0; mi < 4; mi++)
                LDM_X4(af[mi][0], af[mi][1], af[mi][2], af[mi][3],
                       sb + SM_AL + aoff + mi * 16 * ROWB);
#pragma unroll
            for (int mi = 0; mi < 4; mi++)
#pragma unroll
                for (int ni = 0; ni < 4; ni++)
                    MMA_BF16(acc[mi][ni], af[mi], bhf[ni]);
        }
    }

    // Epilogue: bias + tanh + store fp32 to g_y.
    const float* bias = (nBase < 512) ? (b1 + nBase) : (b2 + (nBase - 512));
#pragma unroll
    for (int mi = 0; mi < 4; mi++) {
#pragma unroll
        for (int ni = 0; ni < 4; ni++) {
            int m = mBase + wm * 64 + mi * 16 + (lane >> 2);
            int nl = wn * 32 + ni * 8 + (lane & 3) * 2;
            float bv0 = __ldg(bias + nl);
            float bv1 = __ldg(bias + nl + 1);
            float2 o0, o1;
            o0.x = tanhf(acc[mi][ni][0] + bv0);
            o0.y = tanhf(acc[mi][ni][1] + bv1);
            o1.x = tanhf(acc[mi][ni][2] + bv0);
            o1.y = tanhf(acc[mi][ni][3] + bv1);
            *(float2*)(g_y + (size_t)m * 1024 + nBase + nl)       = o0;
            *(float2*)(g_y + (size_t)(m + 8) * 1024 + nBase + nl) = o1;
        }
    }
}

// ---------------------------------------------------------------------------
// Phase 2: out[b,i,j] = sum_a Wout[a]*tanh(x1[b,j,a] + x2[b,i+1,a]) + bout
// contribution = (wp + wu) * rcp(1 + p*u); 3 fma-pipe + 1 MUFU per element.
// Tile 64i x 32j, per-thread 4i x 2j, 256 blocks -> 2 CTAs/SM.
// Register-pipelined: next chunk's Y values prefetch into regs during the
// compute loop, hiding the fill-phase LDG latency that cost ~23us before.
// ---------------------------------------------------------------------------
#define ACH   64
#define STRJ  34
#define STRI  68
#define AT_SMEM ((2 * ACH * STRJ + 2 * ACH * STRI) * 4)   // 52224 B

__global__ __launch_bounds__(256) void attn_kernel(
    const float* __restrict__ Wout,
    const float* __restrict__ bout,
    float* __restrict__ out)
{
    extern __shared__ float smf[];
    float* s_p  = smf;                           // [ACH][STRJ]
    float* s_wp = smf + ACH * STRJ;
    float* s_u  = smf + 2 * ACH * STRJ;          // [ACH][STRI]
    float* s_wu = s_u + ACH * STRI;

    const int b  = blockIdx.z;
    const int j0 = blockIdx.x * 32;
    const int i0 = blockIdx.y * 64;

    const int tid = threadIdx.x;
    const int jg  = tid & 15;          // j = j0 + 2*jg + {0,1}
    const int ig  = tid >> 4;          // i = i0 + 4*ig + {0..3}

    const float* __restrict__ Y = g_y + (size_t)b * 128 * 1024;

    const int fa = tid & 63;
    const int fr = tid >> 6;           // 0..3

    // clamped i-rows (shift by 1; clamped edge values land in unused slots)
    int irow[16];
#pragma unroll
    for (int t = 0; t < 16; t++) {
        int r2 = i0 + fr + t * 4 + 1;
        irow[t] = (r2 > 127) ? 127 : r2;
    }

    float pr[8], ur[16];
    // prologue: prefetch chunk 0
#pragma unroll
    for (int t = 0; t < 8; t++)
        pr[t] = Y[(size_t)(j0 + fr + t * 4) * 1024 + fa];
#pragma unroll
    for (int t = 0; t < 16; t++)
        ur[t] = Y[(size_t)irow[t] * 1024 + 512 + fa];

    float acc[4][2];
#pragma unroll
    for (int n = 0; n < 4; n++) { acc[n][0] = 0.0f; acc[n][1] = 0.0f; }

    for (int cc = 0; cc < 8; cc++) {
        const int ac = cc * ACH;
        const float w = __ldg(Wout + ac + fa);

        __syncthreads();               // prior compute done reading smem
#pragma unroll
        for (int t = 0; t < 8; t++) {
            int r = fr + t * 4;
            s_p [fa * STRJ + r] = pr[t];
            s_wp[fa * STRJ + r] = w * pr[t];
        }
#pragma unroll
        for (int t = 0; t < 16; t++) {
            int r = fr + t * 4;
            s_u [fa * STRI + r] = ur[t];
            s_wu[fa * STRI + r] = w * ur[t];
        }
        __syncthreads();

        if (cc < 7) {                  // prefetch next chunk; hidden by compute
            const int ac2 = ac + ACH;
#pragma unroll
            for (int t = 0; t < 8; t++)
                pr[t] = Y[(size_t)(j0 + fr + t * 4) * 1024 + ac2 + fa];
#pragma unroll
            for (int t = 0; t < 16; t++)
                ur[t] = Y[(size_t)irow[t] * 1024 + 512 + ac2 + fa];
        }

#pragma unroll 2
        for (int a = 0; a < ACH; a++) {
            float2 p2  = *(const float2*)&s_p [a * STRJ + jg * 2];
            float2 wp2 = *(const float2*)&s_wp[a * STRJ + jg * 2];
            float4 u4  = *(const float4*)&s_u [a * STRI + ig * 4];
            float4 wu4 = *(const float4*)&s_wu[a * STRI + ig * 4];
            float pm[2]  = {p2.x, p2.y};
            float wpm[2] = {wp2.x, wp2.y};
            float un[4]  = {u4.x, u4.y, u4.z, u4.w};
            float wun[4] = {wu4.x, wu4.y, wu4.z, wu4.w};
#pragma unroll
            for (int n = 0; n < 4; n++)
#pragma unroll
                for (int m = 0; m < 2; m++) {
                    float den = fmaf(pm[m], un[n], 1.0f);
                    float num = wpm[m] + wun[n];
                    acc[n][m] = fmaf(num, frcp(den), acc[n][m]);
                }
        }
    }

    const float bo = __ldg(bout);
#pragma unroll
    for (int n = 0; n < 4; n++) {
        int i = i0 + ig * 4 + n;
        if (i < 127) {
            float2 o;
            o.x = acc[n][0] + bo;
            o.y = acc[n][1] + bo;
            *(float2*)(out + ((size_t)b * 127 + i) * 128 + j0 + jg * 2) = o;
        }
    }
}

// ---------------------------------------------------------------------------
extern "C" void kernel_launch(void* const* d_in, const int* in_sizes, int n_in,
                              void* d_out, int out_size)
{
    const float* x    = (const float*)d_in[0];
    const float* W1   = (const float*)d_in[1];
    const float* b1   = (const float*)d_in[2];
    const float* W2   = (const float*)d_in[3];
    const float* b2   = (const float*)d_in[4];
    const float* Wout = (const float*)d_in[5];
    const float* bout = (const float*)d_in[6];
    float* out = (float*)d_out;

    __nv_bfloat16 *wh, *wl;
    cudaGetSymbolAddress((void**)&wh, g_wh);
    cudaGetSymbolAddress((void**)&wl, g_wl);

    static bool attr_set = false;
    if (!attr_set) {
        cudaFuncSetAttribute(gemm_tc_kernel,
                             cudaFuncAttributeMaxDynamicSharedMemorySize, SM_TOTAL);
        cudaFuncSetAttribute(attn_kernel,
                             cudaFuncAttributeMaxDynamicSharedMemorySize, AT_SMEM);
        attr_set = true;
    }

    // Phase 0: weight fp32 -> bf16 hi/lo splits (x is split inside the GEMM)
    split_kernel<<<(512 * 512 + 255) / 256, 256>>>(W1, wh, wl, 512 * 512);
    split_kernel<<<(512 * 512 + 255) / 256, 256>>>(W2, wh + 512 * 512, wl + 512 * 512,
                                                   512 * 512);

    // Phase 1: tensor-core (mma.sync) GEMM + tanh epilogue
    gemm_tc_kernel<<<dim3(32, 8), 256, SM_TOTAL>>>(x, b1, b2);

    // Phase 2: additive attention (64i x 32j tiles, 4x2 per thread, 256 blocks)
    attn_kernel<<<dim3(4, 2, 32), 256, AT_SMEM>>>(Wout, bout, out);
}

// round 8
// speedup vs baseline: 2.4612x; 1.1947x over previous
#include <cuda_runtime.h>
#include <cuda_bf16.h>
#include <cstdint>

// ---------------------------------------------------------------------------
// Scratch (device globals; no allocation allowed)
// ---------------------------------------------------------------------------
__device__ float g_y[4096 * 1024];            // tanh(x@[W1;W2]^T + b), 16MB
__device__ __nv_bfloat16 g_wh[1024 * 512];    // [W1;W2] hi
__device__ __nv_bfloat16 g_wl[1024 * 512];    // [W1;W2] lo

static __device__ __forceinline__ uint32_t s2u(const void* p) {
    return (uint32_t)__cvta_generic_to_shared(p);
}
static __device__ __forceinline__ float frcp(float x) {
    float r;
    asm("rcp.approx.ftz.f32 %0, %1;" : "=f"(r) : "f"(x));
    return r;
}

// ---- packed f32x2 ops (Blackwell) ----
static __device__ __forceinline__ uint64_t fma2(uint64_t a, uint64_t b, uint64_t c) {
    uint64_t d;
    asm("fma.rn.f32x2 %0, %1, %2, %3;" : "=l"(d) : "l"(a), "l"(b), "l"(c));
    return d;
}
static __device__ __forceinline__ uint64_t add2(uint64_t a, uint64_t b) {
    uint64_t d;
    asm("add.rn.f32x2 %0, %1, %2;" : "=l"(d) : "l"(a), "l"(b));
    return d;
}
static __device__ __forceinline__ uint64_t mul2(uint64_t a, uint64_t b) {
    uint64_t d;
    asm("mul.rn.f32x2 %0, %1, %2;" : "=l"(d) : "l"(a), "l"(b));
    return d;
}
static __device__ __forceinline__ uint64_t bcast2(float x) {
    uint64_t d;
    asm("mov.b64 %0, {%1, %1};" : "=l"(d) : "f"(x));
    return d;
}
static __device__ __forceinline__ uint64_t pack2(float x, float y) {
    uint64_t d;
    asm("mov.b64 %0, {%1, %2};" : "=l"(d) : "f"(x), "f"(y));
    return d;
}
static __device__ __forceinline__ float2 unpack2(uint64_t v) {
    float2 r;
    asm("mov.b64 {%0, %1}, %2;" : "=f"(r.x), "=f"(r.y) : "l"(v));
    return r;
}

// ---------------------------------------------------------------------------
// Phase 0: split fp32 -> bf16 hi + bf16 lo (weights only)
// ---------------------------------------------------------------------------
__global__ __launch_bounds__(256) void split_kernel(
    const float* __restrict__ src, __nv_bfloat16* __restrict__ dh,
    __nv_bfloat16* __restrict__ dl, int n)
{
    int i = blockIdx.x * 256 + threadIdx.x;
    if (i < n) {
        float v = src[i];
        __nv_bfloat16 h = __float2bfloat16(v);
        dh[i] = h;
        dl[i] = __float2bfloat16(v - __bfloat162float(h));
    }
}

// ---------------------------------------------------------------------------
// Phase 1: split-bf16 GEMM on mma.sync (HMMA.16816). Unchanged from R7.
// ---------------------------------------------------------------------------
#define ROWB 144
#define TILEB (128 * ROWB)
#define SM_AH 0
#define SM_AL TILEB
#define SM_BH (2 * TILEB)
#define SM_BL (3 * TILEB)
#define SM_TOTAL (4 * TILEB)

#define LDM_X4(r0, r1, r2, r3, addr) \
    asm volatile("ldmatrix.sync.aligned.m8n8.x4.shared.b16 {%0,%1,%2,%3}, [%4];" \
                 : "=r"(r0), "=r"(r1), "=r"(r2), "=r"(r3) : "r"(addr))

#define MMA_BF16(c, a, b) \
    asm volatile("mma.sync.aligned.m16n8k16.row.col.f32.bf16.bf16.f32 " \
                 "{%0,%1,%2,%3}, {%4,%5,%6,%7}, {%8,%9}, {%0,%1,%2,%3};" \
                 : "+f"((c)[0]), "+f"((c)[1]), "+f"((c)[2]), "+f"((c)[3]) \
                 : "r"((a)[0]), "r"((a)[1]), "r"((a)[2]), "r"((a)[3]), \
                   "r"((b)[0]), "r"((b)[1]))

__global__ __launch_bounds__(256, 2) void gemm_tc_kernel(
    const float* __restrict__ x,
    const float* __restrict__ b1, const float* __restrict__ b2)
{
    extern __shared__ char sm[];
    const uint32_t sb = s2u(sm);
    const int tid  = threadIdx.x;
    const int wid  = tid >> 5;
    const int lane = tid & 31;

    const int mBase = blockIdx.x * 128;
    const int nBase = blockIdx.y * 128;

    const int wm = wid & 1;
    const int wn = wid >> 1;

    const int lr  = lane & 7;
    const int ls3 = (lane >> 3) & 1;
    const int ls4 = (lane >> 4) & 1;

    float acc[4][4][4];
#pragma unroll
    for (int mi = 0; mi < 4; mi++)
#pragma unroll
        for (int ni = 0; ni < 4; ni++)
#pragma unroll
            for (int f = 0; f < 4; f++) acc[mi][ni][f] = 0.0f;

    for (int kc = 0; kc < 8; kc++) {
        __syncthreads();

        float4 va[8];
#pragma unroll
        for (int t = 0; t < 8; t++) {
            int idx = tid + t * 256;
            int row = idx >> 4;
            int c4  = idx & 15;
            va[t] = *(const float4*)(x + (size_t)(mBase + row) * 512 + kc * 64 + c4 * 4);
        }
#pragma unroll
        for (int t = 0; t < 8; t++) {
            int idx  = tid + t * 256;
            int tile = idx >> 10;
            int u    = idx & 1023;
            int row  = u >> 3;
            int c16  = u & 7;
            const __nv_bfloat16* gsrc = (tile == 0 ? g_wh : g_wl) + (size_t)(nBase + row) * 512;
            *(uint4*)(sm + (2 + tile) * TILEB + row * ROWB + c16 * 16) =
                *(const uint4*)(gsrc + kc * 64 + c16 * 8);
        }
#pragma unroll
        for (int t = 0; t < 8; t++) {
            int idx = tid + t * 256;
            int row = idx >> 4;
            int c4  = idx & 15;
            uint32_t off = row * ROWB + c4 * 8;
            __nv_bfloat162 h01 = __float22bfloat162_rn(make_float2(va[t].x, va[t].y));
            __nv_bfloat162 h23 = __float22bfloat162_rn(make_float2(va[t].z, va[t].w));
            float2 hf01 = __bfloat1622float2(h01);
            float2 hf23 = __bfloat1622float2(h23);
            __nv_bfloat162 l01 = __float22bfloat162_rn(
                make_float2(va[t].x - hf01.x, va[t].y - hf01.y));
            __nv_bfloat162 l23 = __float22bfloat162_rn(
                make_float2(va[t].z - hf23.x, va[t].w - hf23.y));
            uint2 hh, ll;
            hh.x = *(uint32_t*)&h01; hh.y = *(uint32_t*)&h23;
            ll.x = *(uint32_t*)&l01; ll.y = *(uint32_t*)&l23;
            *(uint2*)(sm + SM_AH + off) = hh;
            *(uint2*)(sm + SM_AL + off) = ll;
        }
        __syncthreads();

#pragma unroll
        for (int ks = 0; ks < 4; ks++) {
            const int kb = ks * 16;
            uint32_t aoff = (uint32_t)((wm * 64 + ls3 * 8 + lr) * ROWB + (kb + ls4 * 8) * 2);
            uint32_t boff = (uint32_t)((wn * 32 + ls4 * 8 + lr) * ROWB + (kb + ls3 * 8) * 2);

            uint32_t bhf[4][2], blf[4][2];
#pragma unroll
            for (int nb = 0; nb < 2; nb++) {
                LDM_X4(bhf[2 * nb][0], bhf[2 * nb][1], bhf[2 * nb + 1][0], bhf[2 * nb + 1][1],
                       sb + SM_BH + boff + nb * 16 * ROWB);
                LDM_X4(blf[2 * nb][0], blf[2 * nb][1], blf[2 * nb + 1][0], blf[2 * nb + 1][1],
                       sb + SM_BL + boff + nb * 16 * ROWB);
            }

            uint32_t af[4][4];
#pragma unroll
            for (int mi = 0; mi < 4; mi++)
                LDM_X4(af[mi][0], af[mi][1], af[mi][2], af[mi][3],
                       sb + SM_AH + aoff + mi * 16 * ROWB);
#pragma unroll
            for (int mi = 0; mi < 4; mi++)
#pragma unroll
                for (int ni = 0; ni < 4; ni++)
                    MMA_BF16(acc[mi][ni], af[mi], bhf[ni]);
#pragma unroll
            for (int mi = 0; mi < 4; mi++)
#pragma unroll
                for (int ni = 0; ni < 4; ni++)
                    MMA_BF16(acc[mi][ni], af[mi], blf[ni]);
#pragma unroll
            for (int mi = 0; mi < 4; mi++)
                LDM_X4(af[mi][0], af[mi][1], af[mi][2], af[mi][3],
                       sb + SM_AL + aoff + mi * 16 * ROWB);
#pragma unroll
            for (int mi = 0; mi < 4; mi++)
#pragma unroll
                for (int ni = 0; ni < 4; ni++)
                    MMA_BF16(acc[mi][ni], af[mi], bhf[ni]);
        }
    }

    const float* bias = (nBase < 512) ? (b1 + nBase) : (b2 + (nBase - 512));
#pragma unroll
    for (int mi = 0; mi < 4; mi++) {
#pragma unroll
        for (int ni = 0; ni < 4; ni++) {
            int m = mBase + wm * 64 + mi * 16 + (lane >> 2);
            int nl = wn * 32 + ni * 8 + (lane & 3) * 2;
            float bv0 = __ldg(bias + nl);
            float bv1 = __ldg(bias + nl + 1);
            float2 o0, o1;
            o0.x = tanhf(acc[mi][ni][0] + bv0);
            o0.y = tanhf(acc[mi][ni][1] + bv1);
            o1.x = tanhf(acc[mi][ni][2] + bv0);
            o1.y = tanhf(acc[mi][ni][3] + bv1);
            *(float2*)(g_y + (size_t)m * 1024 + nBase + nl)       = o0;
            *(float2*)(g_y + (size_t)(m + 8) * 1024 + nBase + nl) = o1;
        }
    }
}

// ---------------------------------------------------------------------------
// Phase 2: out[b,i,j] = sum_a Wout[a]*tanh(x1[b,j,a] + x2[b,i+1,a]) + bout
// a-pair reduction: n1/d1 + n2/d2 = (n1*d2 + n2*d1) * rcp(d1*d2)
//   -> 1 MUFU per 2 a-terms. fma ops packed f32x2 across the i-pair lane
//   -> ~4 cyc/warp-term floor on both pipes (was 8).
// Tile 64i x 32j, per-thread 4i x 2j, 256 blocks, reg-pipelined fill.
// ---------------------------------------------------------------------------
#define ACH   64
#define STRJ  34
#define STRI  68
#define AT_SMEM ((2 * ACH * STRJ + 2 * ACH * STRI) * 4)   // 52224 B

__global__ __launch_bounds__(256) void attn_kernel(
    const float* __restrict__ Wout,
    const float* __restrict__ bout,
    float* __restrict__ out)
{
    extern __shared__ float smf[];
    float* s_p  = smf;                           // [ACH][STRJ]
    float* s_wp = smf + ACH * STRJ;
    float* s_u  = smf + 2 * ACH * STRJ;          // [ACH][STRI]
    float* s_wu = s_u + ACH * STRI;

    const int b  = blockIdx.z;
    const int j0 = blockIdx.x * 32;
    const int i0 = blockIdx.y * 64;

    const int tid = threadIdx.x;
    const int jg  = tid & 15;          // j = j0 + 2*jg + {0,1}
    const int ig  = tid >> 4;          // i = i0 + 4*ig + {0..3}

    const float* __restrict__ Y = g_y + (size_t)b * 128 * 1024;

    const int fa = tid & 63;
    const int fr = tid >> 6;

    int irow[16];
#pragma unroll
    for (int t = 0; t < 16; t++) {
        int r2 = i0 + fr + t * 4 + 1;
        irow[t] = (r2 > 127) ? 127 : r2;
    }

    float pr[8], ur[16];
#pragma unroll
    for (int t = 0; t < 8; t++)
        pr[t] = Y[(size_t)(j0 + fr + t * 4) * 1024 + fa];
#pragma unroll
    for (int t = 0; t < 16; t++)
        ur[t] = Y[(size_t)irow[t] * 1024 + 512 + fa];

    const uint64_t ONE2 = 0x3F8000003F800000ull;
    // acc2[j][ipair]: packed {i_lo, i_hi} accumulators
    uint64_t acc2[2][2] = {{0ull, 0ull}, {0ull, 0ull}};

    for (int cc = 0; cc < 8; cc++) {
        const int ac = cc * ACH;
        const float w = __ldg(Wout + ac + fa);

        __syncthreads();
#pragma unroll
        for (int t = 0; t < 8; t++) {
            int r = fr + t * 4;
            s_p [fa * STRJ + r] = pr[t];
            s_wp[fa * STRJ + r] = w * pr[t];
        }
#pragma unroll
        for (int t = 0; t < 16; t++) {
            int r = fr + t * 4;
            s_u [fa * STRI + r] = ur[t];
            s_wu[fa * STRI + r] = w * ur[t];
        }
        __syncthreads();

        if (cc < 7) {
            const int ac2 = ac + ACH;
#pragma unroll
            for (int t = 0; t < 8; t++)
                pr[t] = Y[(size_t)(j0 + fr + t * 4) * 1024 + ac2 + fa];
#pragma unroll
            for (int t = 0; t < 16; t++)
                ur[t] = Y[(size_t)irow[t] * 1024 + 512 + ac2 + fa];
        }

#pragma unroll 2
        for (int a = 0; a < ACH; a += 2) {
            // p / wp for both a-steps, both j's (broadcast-packed)
            float2 pA  = *(const float2*)&s_p [ a      * STRJ + jg * 2];
            float2 pB  = *(const float2*)&s_p [(a + 1) * STRJ + jg * 2];
            float2 wpA = *(const float2*)&s_wp[ a      * STRJ + jg * 2];
            float2 wpB = *(const float2*)&s_wp[(a + 1) * STRJ + jg * 2];
            uint64_t pAb[2]  = {bcast2(pA.x),  bcast2(pA.y)};
            uint64_t pBb[2]  = {bcast2(pB.x),  bcast2(pB.y)};
            uint64_t wpAb[2] = {bcast2(wpA.x), bcast2(wpA.y)};
            uint64_t wpBb[2] = {bcast2(wpB.x), bcast2(wpB.y)};
            // u / wu: float4 = two packed i-pairs (natural b64 pairs)
            ulonglong2 uA  = *(const ulonglong2*)&s_u [ a      * STRI + ig * 4];
            ulonglong2 uB  = *(const ulonglong2*)&s_u [(a + 1) * STRI + ig * 4];
            ulonglong2 wuA = *(const ulonglong2*)&s_wu[ a      * STRI + ig * 4];
            ulonglong2 wuB = *(const ulonglong2*)&s_wu[(a + 1) * STRI + ig * 4];
            uint64_t uAp[2]  = {uA.x,  uA.y};
            uint64_t uBp[2]  = {uB.x,  uB.y};
            uint64_t wuAp[2] = {wuA.x, wuA.y};
            uint64_t wuBp[2] = {wuB.x, wuB.y};

#pragma unroll
            for (int j = 0; j < 2; j++)
#pragma unroll
                for (int ip = 0; ip < 2; ip++) {
                    uint64_t d1 = fma2(uAp[ip], pAb[j], ONE2);
                    uint64_t d2 = fma2(uBp[ip], pBb[j], ONE2);
                    uint64_t n1 = add2(wuAp[ip], wpAb[j]);
                    uint64_t n2 = add2(wuBp[ip], wpBb[j]);
                    uint64_t t  = mul2(d1, d2);
                    float2 tf = unpack2(t);
                    uint64_t r  = pack2(frcp(tf.x), frcp(tf.y));
                    uint64_t e  = mul2(n1, d2);
                    e = fma2(n2, d1, e);
                    acc2[j][ip] = fma2(e, r, acc2[j][ip]);
                }
        }
    }

    const float bo = __ldg(bout);
#pragma unroll
    for (int ip = 0; ip < 2; ip++) {
        float2 aj0 = unpack2(acc2[0][ip]);
        float2 aj1 = unpack2(acc2[1][ip]);
        // lanes: i = i0 + ig*4 + ip*2 + {0,1}
#pragma unroll
        for (int l = 0; l < 2; l++) {
            int i = i0 + ig * 4 + ip * 2 + l;
            if (i < 127) {
                float2 o;
                o.x = (l == 0 ? aj0.x : aj0.y) + bo;
                o.y = (l == 0 ? aj1.x : aj1.y) + bo;
                *(float2*)(out + ((size_t)b * 127 + i) * 128 + j0 + jg * 2) = o;
            }
        }
    }
}

// ---------------------------------------------------------------------------
extern "C" void kernel_launch(void* const* d_in, const int* in_sizes, int n_in,
                              void* d_out, int out_size)
{
    const float* x    = (const float*)d_in[0];
    const float* W1   = (const float*)d_in[1];
    const float* b1   = (const float*)d_in[2];
    const float* W2   = (const float*)d_in[3];
    const float* b2   = (const float*)d_in[4];
    const float* Wout = (const float*)d_in[5];
    const float* bout = (const float*)d_in[6];
    float* out = (float*)d_out;

    __nv_bfloat16 *wh, *wl;
    cudaGetSymbolAddress((void**)&wh, g_wh);
    cudaGetSymbolAddress((void**)&wl, g_wl);

    static bool attr_set = false;
    if (!attr_set) {
        cudaFuncSetAttribute(gemm_tc_kernel,
                             cudaFuncAttributeMaxDynamicSharedMemorySize, SM_TOTAL);
        cudaFuncSetAttribute(attn_kernel,
                             cudaFuncAttributeMaxDynamicSharedMemorySize, AT_SMEM);
        attr_set = true;
    }

    split_kernel<<<(512 * 512 + 255) / 256, 256>>>(W1, wh, wl, 512 * 512);
    split_kernel<<<(512 * 512 + 255) / 256, 256>>>(W2, wh + 512 * 512, wl + 512 * 512,
                                                   512 * 512);

    gemm_tc_kernel<<<dim3(32, 8), 256, SM_TOTAL>>>(x, b1, b2);

    attn_kernel<<<dim3(4, 2, 32), 256, AT_SMEM>>>(Wout, bout, out);
}

// round 9
// speedup vs baseline: 2.5446x; 1.0339x over previous
#include <cuda_runtime.h>
#include <cuda_bf16.h>
#include <cstdint>

// ---------------------------------------------------------------------------
// Scratch (device globals; no allocation allowed)
// ---------------------------------------------------------------------------
__device__ float g_y[4096 * 1024];            // tanh(x@[W1;W2]^T + b), 16MB
__device__ __nv_bfloat16 g_wh[1024 * 512];    // [W1;W2] hi
__device__ __nv_bfloat16 g_wl[1024 * 512];    // [W1;W2] lo

static __device__ __forceinline__ uint32_t s2u(const void* p) {
    return (uint32_t)__cvta_generic_to_shared(p);
}
static __device__ __forceinline__ float frcp(float x) {
    float r;
    asm("rcp.approx.ftz.f32 %0, %1;" : "=f"(r) : "f"(x));
    return r;
}

// ---- packed f32x2 ops (Blackwell) ----
static __device__ __forceinline__ uint64_t fma2(uint64_t a, uint64_t b, uint64_t c) {
    uint64_t d;
    asm("fma.rn.f32x2 %0, %1, %2, %3;" : "=l"(d) : "l"(a), "l"(b), "l"(c));
    return d;
}
static __device__ __forceinline__ uint64_t add2(uint64_t a, uint64_t b) {
    uint64_t d;
    asm("add.rn.f32x2 %0, %1, %2;" : "=l"(d) : "l"(a), "l"(b));
    return d;
}
static __device__ __forceinline__ uint64_t mul2(uint64_t a, uint64_t b) {
    uint64_t d;
    asm("mul.rn.f32x2 %0, %1, %2;" : "=l"(d) : "l"(a), "l"(b));
    return d;
}
static __device__ __forceinline__ uint64_t bcast2(float x) {
    uint64_t d;
    asm("mov.b64 %0, {%1, %1};" : "=l"(d) : "f"(x));
    return d;
}
static __device__ __forceinline__ uint64_t pack2(float x, float y) {
    uint64_t d;
    asm("mov.b64 %0, {%1, %2};" : "=l"(d) : "f"(x), "f"(y));
    return d;
}
static __device__ __forceinline__ float2 unpack2(uint64_t v) {
    float2 r;
    asm("mov.b64 {%0, %1}, %2;" : "=f"(r.x), "=f"(r.y) : "l"(v));
    return r;
}

// ---------------------------------------------------------------------------
// Phase 0: split W1+W2 fp32 -> bf16 hi/lo (single launch)
// ---------------------------------------------------------------------------
__global__ __launch_bounds__(256) void split_w_kernel(
    const float* __restrict__ W1, const float* __restrict__ W2,
    __nv_bfloat16* __restrict__ dh, __nv_bfloat16* __restrict__ dl)
{
    int i = blockIdx.x * 256 + threadIdx.x;   // [0, 524288)
    float v = (i < 262144) ? W1[i] : W2[i - 262144];
    __nv_bfloat16 h = __float2bfloat16(v);
    dh[i] = h;
    dl[i] = __float2bfloat16(v - __bfloat162float(h));
}

// ---------------------------------------------------------------------------
// Phase 1: split-bf16 GEMM on mma.sync (HMMA.16816). Unchanged (43.4us).
// ---------------------------------------------------------------------------
#define ROWB 144
#define TILEB (128 * ROWB)
#define SM_AH 0
#define SM_AL TILEB
#define SM_BH (2 * TILEB)
#define SM_BL (3 * TILEB)
#define SM_TOTAL (4 * TILEB)

#define LDM_X4(r0, r1, r2, r3, addr) \
    asm volatile("ldmatrix.sync.aligned.m8n8.x4.shared.b16 {%0,%1,%2,%3}, [%4];" \
                 : "=r"(r0), "=r"(r1), "=r"(r2), "=r"(r3) : "r"(addr))

#define MMA_BF16(c, a, b) \
    asm volatile("mma.sync.aligned.m16n8k16.row.col.f32.bf16.bf16.f32 " \
                 "{%0,%1,%2,%3}, {%4,%5,%6,%7}, {%8,%9}, {%0,%1,%2,%3};" \
                 : "+f"((c)[0]), "+f"((c)[1]), "+f"((c)[2]), "+f"((c)[3]) \
                 : "r"((a)[0]), "r"((a)[1]), "r"((a)[2]), "r"((a)[3]), \
                   "r"((b)[0]), "r"((b)[1]))

__global__ __launch_bounds__(256, 2) void gemm_tc_kernel(
    const float* __restrict__ x,
    const float* __restrict__ b1, const float* __restrict__ b2)
{
    extern __shared__ char sm[];
    const uint32_t sb = s2u(sm);
    const int tid  = threadIdx.x;
    const int wid  = tid >> 5;
    const int lane = tid & 31;

    const int mBase = blockIdx.x * 128;
    const int nBase = blockIdx.y * 128;

    const int wm = wid & 1;
    const int wn = wid >> 1;

    const int lr  = lane & 7;
    const int ls3 = (lane >> 3) & 1;
    const int ls4 = (lane >> 4) & 1;

    float acc[4][4][4];
#pragma unroll
    for (int mi = 0; mi < 4; mi++)
#pragma unroll
        for (int ni = 0; ni < 4; ni++)
#pragma unroll
            for (int f = 0; f < 4; f++) acc[mi][ni][f] = 0.0f;

    for (int kc = 0; kc < 8; kc++) {
        __syncthreads();

        float4 va[8];
#pragma unroll
        for (int t = 0; t < 8; t++) {
            int idx = tid + t * 256;
            int row = idx >> 4;
            int c4  = idx & 15;
            va[t] = *(const float4*)(x + (size_t)(mBase + row) * 512 + kc * 64 + c4 * 4);
        }
#pragma unroll
        for (int t = 0; t < 8; t++) {
            int idx  = tid + t * 256;
            int tile = idx >> 10;
            int u    = idx & 1023;
            int row  = u >> 3;
            int c16  = u & 7;
            const __nv_bfloat16* gsrc = (tile == 0 ? g_wh : g_wl) + (size_t)(nBase + row) * 512;
            *(uint4*)(sm + (2 + tile) * TILEB + row * ROWB + c16 * 16) =
                *(const uint4*)(gsrc + kc * 64 + c16 * 8);
        }
#pragma unroll
        for (int t = 0; t < 8; t++) {
            int idx = tid + t * 256;
            int row = idx >> 4;
            int c4  = idx & 15;
            uint32_t off = row * ROWB + c4 * 8;
            __nv_bfloat162 h01 = __float22bfloat162_rn(make_float2(va[t].x, va[t].y));
            __nv_bfloat162 h23 = __float22bfloat162_rn(make_float2(va[t].z, va[t].w));
            float2 hf01 = __bfloat1622float2(h01);
            float2 hf23 = __bfloat1622float2(h23);
            __nv_bfloat162 l01 = __float22bfloat162_rn(
                make_float2(va[t].x - hf01.x, va[t].y - hf01.y));
            __nv_bfloat162 l23 = __float22bfloat162_rn(
                make_float2(va[t].z - hf23.x, va[t].w - hf23.y));
            uint2 hh, ll;
            hh.x = *(uint32_t*)&h01; hh.y = *(uint32_t*)&h23;
            ll.x = *(uint32_t*)&l01; ll.y = *(uint32_t*)&l23;
            *(uint2*)(sm + SM_AH + off) = hh;
            *(uint2*)(sm + SM_AL + off) = ll;
        }
        __syncthreads();

#pragma unroll
        for (int ks = 0; ks < 4; ks++) {
            const int kb = ks * 16;
            uint32_t aoff = (uint32_t)((wm * 64 + ls3 * 8 + lr) * ROWB + (kb + ls4 * 8) * 2);
            uint32_t boff = (uint32_t)((wn * 32 + ls4 * 8 + lr) * ROWB + (kb + ls3 * 8) * 2);

            uint32_t bhf[4][2], blf[4][2];
#pragma unroll
            for (int nb = 0; nb < 2; nb++) {
                LDM_X4(bhf[2 * nb][0], bhf[2 * nb][1], bhf[2 * nb + 1][0], bhf[2 * nb + 1][1],
                       sb + SM_BH + boff + nb * 16 * ROWB);
                LDM_X4(blf[2 * nb][0], blf[2 * nb][1], blf[2 * nb + 1][0], blf[2 * nb + 1][1],
                       sb + SM_BL + boff + nb * 16 * ROWB);
            }

            uint32_t af[4][4];
#pragma unroll
            for (int mi = 0; mi < 4; mi++)
                LDM_X4(af[mi][0], af[mi][1], af[mi][2], af[mi][3],
                       sb + SM_AH + aoff + mi * 16 * ROWB);
#pragma unroll
            for (int mi = 0; mi < 4; mi++)
#pragma unroll
                for (int ni = 0; ni < 4; ni++)
                    MMA_BF16(acc[mi][ni], af[mi], bhf[ni]);
#pragma unroll
            for (int mi = 0; mi < 4; mi++)
#pragma unroll
                for (int ni = 0; ni < 4; ni++)
                    MMA_BF16(acc[mi][ni], af[mi], blf[ni]);
#pragma unroll
            for (int mi = 0; mi < 4; mi++)
                LDM_X4(af[mi][0], af[mi][1], af[mi][2], af[mi][3],
                       sb + SM_AL + aoff + mi * 16 * ROWB);
#pragma unroll
            for (int mi = 0; mi < 4; mi++)
#pragma unroll
                for (int ni = 0; ni < 4; ni++)
                    MMA_BF16(acc[mi][ni], af[mi], bhf[ni]);
        }
    }

    const float* bias = (nBase < 512) ? (b1 + nBase) : (b2 + (nBase - 512));
#pragma unroll
    for (int mi = 0; mi < 4; mi++) {
#pragma unroll
        for (int ni = 0; ni < 4; ni++) {
            int m = mBase + wm * 64 + mi * 16 + (lane >> 2);
            int nl = wn * 32 + ni * 8 + (lane & 3) * 2;
            float bv0 = __ldg(bias + nl);
            float bv1 = __ldg(bias + nl + 1);
            float2 o0, o1;
            o0.x = tanhf(acc[mi][ni][0] + bv0);
            o0.y = tanhf(acc[mi][ni][1] + bv1);
            o1.x = tanhf(acc[mi][ni][2] + bv0);
            o1.y = tanhf(acc[mi][ni][3] + bv1);
            *(float2*)(g_y + (size_t)m * 1024 + nBase + nl)       = o0;
            *(float2*)(g_y + (size_t)(m + 8) * 1024 + nBase + nl) = o1;
        }
    }
}

// ---------------------------------------------------------------------------
// Phase 2: out[b,i,j] = sum_a Wout[a]*tanh(x1[b,j,a] + x2[b,i+1,a]) + bout
// a-pair reduction with packed f32x2. wu = w*u rebuilt in-register from a
// broadcast w (1 LDS.64/iter) -> s_wu array eliminated: LDS bytes -25%,
// STS -33%, smem 52->35KB. n = wp + w*u; d = 1 + p*u.
// ---------------------------------------------------------------------------
#define ACH   64
#define STRJ  34
#define STRI  68
// s_p + s_wp: ACH*STRJ each; s_u: ACH*STRI; s_w: ACH
#define AT_SMEM ((2 * ACH * STRJ + ACH * STRI + ACH) * 4)   // 35072 B

__global__ __launch_bounds__(256) void attn_kernel(
    const float* __restrict__ Wout,
    const float* __restrict__ bout,
    float* __restrict__ out)
{
    extern __shared__ float smf[];
    float* s_p  = smf;                           // [ACH][STRJ]
    float* s_wp = smf + ACH * STRJ;              // [ACH][STRJ]
    float* s_u  = smf + 2 * ACH * STRJ;          // [ACH][STRI]
    float* s_w  = s_u + ACH * STRI;              // [ACH]

    const int b  = blockIdx.z;
    const int j0 = blockIdx.x * 32;
    const int i0 = blockIdx.y * 64;

    const int tid = threadIdx.x;
    const int jg  = tid & 15;          // j = j0 + 2*jg + {0,1}
    const int ig  = tid >> 4;          // i = i0 + 4*ig + {0..3}

    const float* __restrict__ Y = g_y + (size_t)b * 128 * 1024;

    const int fa = tid & 63;
    const int fr = tid >> 6;

    int irow[16];
#pragma unroll
    for (int t = 0; t < 16; t++) {
        int r2 = i0 + fr + t * 4 + 1;
        irow[t] = (r2 > 127) ? 127 : r2;
    }

    float pr[8], ur[16];
#pragma unroll
    for (int t = 0; t < 8; t++)
        pr[t] = Y[(size_t)(j0 + fr + t * 4) * 1024 + fa];
#pragma unroll
    for (int t = 0; t < 16; t++)
        ur[t] = Y[(size_t)irow[t] * 1024 + 512 + fa];

    const uint64_t ONE2 = 0x3F8000003F800000ull;
    uint64_t acc2[2][2] = {{0ull, 0ull}, {0ull, 0ull}};

    for (int cc = 0; cc < 8; cc++) {
        const int ac = cc * ACH;
        const float w = __ldg(Wout + ac + fa);

        __syncthreads();
#pragma unroll
        for (int t = 0; t < 8; t++) {
            int r = fr + t * 4;
            s_p [fa * STRJ + r] = pr[t];
            s_wp[fa * STRJ + r] = w * pr[t];
        }
#pragma unroll
        for (int t = 0; t < 16; t++)
            s_u[fa * STRI + fr + t * 4] = ur[t];
        if (tid < ACH) s_w[tid] = w;       // fa == tid for tid < 64
        __syncthreads();

        if (cc < 7) {
            const int ac2 = ac + ACH;
#pragma unroll
            for (int t = 0; t < 8; t++)
                pr[t] = Y[(size_t)(j0 + fr + t * 4) * 1024 + ac2 + fa];
#pragma unroll
            for (int t = 0; t < 16; t++)
                ur[t] = Y[(size_t)irow[t] * 1024 + 512 + ac2 + fa];
        }

#pragma unroll 2
        for (int a = 0; a < ACH; a += 2) {
            float2 wpair = *(const float2*)&s_w[a];
            float2 pA  = *(const float2*)&s_p [ a      * STRJ + jg * 2];
            float2 pB  = *(const float2*)&s_p [(a + 1) * STRJ + jg * 2];
            float2 wpA = *(const float2*)&s_wp[ a      * STRJ + jg * 2];
            float2 wpB = *(const float2*)&s_wp[(a + 1) * STRJ + jg * 2];
            ulonglong2 uA = *(const ulonglong2*)&s_u[ a      * STRI + ig * 4];
            ulonglong2 uB = *(const ulonglong2*)&s_u[(a + 1) * STRI + ig * 4];

            uint64_t pAb[2]  = {bcast2(pA.x),  bcast2(pA.y)};
            uint64_t pBb[2]  = {bcast2(pB.x),  bcast2(pB.y)};
            uint64_t wpAb[2] = {bcast2(wpA.x), bcast2(wpA.y)};
            uint64_t wpBb[2] = {bcast2(wpB.x), bcast2(wpB.y)};
            uint64_t wAb = bcast2(wpair.x);
            uint64_t wBb = bcast2(wpair.y);
            uint64_t uAp[2] = {uA.x, uA.y};
            uint64_t uBp[2] = {uB.x, uB.y};
            // rebuild wu in-register (replaces the s_wu smem array)
            uint64_t wuA[2] = {mul2(wAb, uAp[0]), mul2(wAb, uAp[1])};
            uint64_t wuB[2] = {mul2(wBb, uBp[0]), mul2(wBb, uBp[1])};

#pragma unroll
            for (int j = 0; j < 2; j++)
#pragma unroll
                for (int ip = 0; ip < 2; ip++) {
                    uint64_t d1 = fma2(uAp[ip], pAb[j], ONE2);
                    uint64_t d2 = fma2(uBp[ip], pBb[j], ONE2);
                    uint64_t n1 = add2(wuA[ip], wpAb[j]);
                    uint64_t n2 = add2(wuB[ip], wpBb[j]);
                    uint64_t t  = mul2(d1, d2);
                    float2 tf = unpack2(t);
                    uint64_t r  = pack2(frcp(tf.x), frcp(tf.y));
                    uint64_t e  = mul2(n1, d2);
                    e = fma2(n2, d1, e);
                    acc2[j][ip] = fma2(e, r, acc2[j][ip]);
                }
        }
    }

    const float bo = __ldg(bout);
#pragma unroll
    for (int ip = 0; ip < 2; ip++) {
        float2 aj0 = unpack2(acc2[0][ip]);
        float2 aj1 = unpack2(acc2[1][ip]);
#pragma unroll
        for (int l = 0; l < 2; l++) {
            int i = i0 + ig * 4 + ip * 2 + l;
            if (i < 127) {
                float2 o;
                o.x = (l == 0 ? aj0.x : aj0.y) + bo;
                o.y = (l == 0 ? aj1.x : aj1.y) + bo;
                *(float2*)(out + ((size_t)b * 127 + i) * 128 + j0 + jg * 2) = o;
            }
        }
    }
}

// ---------------------------------------------------------------------------
extern "C" void kernel_launch(void* const* d_in, const int* in_sizes, int n_in,
                              void* d_out, int out_size)
{
    const float* x    = (const float*)d_in[0];
    const float* W1   = (const float*)d_in[1];
    const float* b1   = (const float*)d_in[2];
    const float* W2   = (const float*)d_in[3];
    const float* b2   = (const float*)d_in[4];
    const float* Wout = (const float*)d_in[5];
    const float* bout = (const float*)d_in[6];
    float* out = (float*)d_out;

    __nv_bfloat16 *wh, *wl;
    cudaGetSymbolAddress((void**)&wh, g_wh);
    cudaGetSymbolAddress((void**)&wl, g_wl);

    static bool attr_set = false;
    if (!attr_set) {
        cudaFuncSetAttribute(gemm_tc_kernel,
                             cudaFuncAttributeMaxDynamicSharedMemorySize, SM_TOTAL);
        cudaFuncSetAttribute(attn_kernel,
                             cudaFuncAttributeMaxDynamicSharedMemorySize, AT_SMEM);
        attr_set = true;
    }

    split_w_kernel<<<524288 / 256, 256>>>(W1, W2, wh, wl);

    gemm_tc_kernel<<<dim3(32, 8), 256, SM_TOTAL>>>(x, b1, b2);

    attn_kernel<<<dim3(4, 2, 32), 256, AT_SMEM>>>(Wout, bout, out);
}